// round 1
// baseline (speedup 1.0000x reference)
#include <cuda_runtime.h>

// Intermediate T = x @ V^T : [8192, 256] fp32 (8 MB scratch, allocation-free)
__device__ float g_T[8192 * 256];

// NT GEMM: C[M,N] = A[M,K] @ B[N,K]^T (+ bias[n])
// Block tile 128x128, K-tile 16, 256 threads, 8x8 accumulators per thread.
// Shapes are exact multiples of tiles for this problem; no bounds checks.
template <bool HAS_BIAS>
__global__ __launch_bounds__(256, 2)
void sgemm_nt(const float* __restrict__ A, const float* __restrict__ B,
              const float* __restrict__ bias, float* __restrict__ C,
              int N, int K) {
    constexpr int KT = 16;
    __shared__ float As[KT][132];  // [k][m], pad 4 keeps float4 rows 16B aligned
    __shared__ float Bs[KT][132];  // [k][n]

    const int tid = threadIdx.x;
    const int tx  = tid & 15;   // 0..15 -> n micro
    const int ty  = tid >> 4;   // 0..15 -> m micro
    const long m0 = (long)blockIdx.y * 128;
    const long n0 = (long)blockIdx.x * 128;

    float acc[8][8];
#pragma unroll
    for (int i = 0; i < 8; i++)
#pragma unroll
        for (int j = 0; j < 8; j++) acc[i][j] = 0.0f;

    // Global->shared load mapping: 128 rows x 16 cols = 512 float4 per tile.
    const int r0 = tid >> 2;          // 0..63 (row within half-tile)
    const int kq = (tid & 3) * 4;     // 0,4,8,12 (k offset of the float4)

    for (int k0 = 0; k0 < K; k0 += KT) {
#pragma unroll
        for (int h = 0; h < 2; h++) {
            const int row = r0 + h * 64;
            const float4 va = *reinterpret_cast<const float4*>(
                &A[(m0 + row) * (long)K + k0 + kq]);
            As[kq + 0][row] = va.x;
            As[kq + 1][row] = va.y;
            As[kq + 2][row] = va.z;
            As[kq + 3][row] = va.w;
            const float4 vb = *reinterpret_cast<const float4*>(
                &B[(n0 + row) * (long)K + k0 + kq]);
            Bs[kq + 0][row] = vb.x;
            Bs[kq + 1][row] = vb.y;
            Bs[kq + 2][row] = vb.z;
            Bs[kq + 3][row] = vb.w;
        }
        __syncthreads();

#pragma unroll
        for (int kk = 0; kk < KT; kk++) {
            float a[8], b[8];
            const float4 a0 = *reinterpret_cast<const float4*>(&As[kk][ty * 8]);
            const float4 a1 = *reinterpret_cast<const float4*>(&As[kk][ty * 8 + 4]);
            const float4 b0 = *reinterpret_cast<const float4*>(&Bs[kk][tx * 8]);
            const float4 b1 = *reinterpret_cast<const float4*>(&Bs[kk][tx * 8 + 4]);
            a[0] = a0.x; a[1] = a0.y; a[2] = a0.z; a[3] = a0.w;
            a[4] = a1.x; a[5] = a1.y; a[6] = a1.z; a[7] = a1.w;
            b[0] = b0.x; b[1] = b0.y; b[2] = b0.z; b[3] = b0.w;
            b[4] = b1.x; b[5] = b1.y; b[6] = b1.z; b[7] = b1.w;
#pragma unroll
            for (int i = 0; i < 8; i++)
#pragma unroll
                for (int j = 0; j < 8; j++) acc[i][j] = fmaf(a[i], b[j], acc[i][j]);
        }
        __syncthreads();
    }

    // Epilogue: optional bias, float4 stores.
    float bv[8];
    if (HAS_BIAS) {
        const float4 c0 = *reinterpret_cast<const float4*>(&bias[n0 + tx * 8]);
        const float4 c1 = *reinterpret_cast<const float4*>(&bias[n0 + tx * 8 + 4]);
        bv[0] = c0.x; bv[1] = c0.y; bv[2] = c0.z; bv[3] = c0.w;
        bv[4] = c1.x; bv[5] = c1.y; bv[6] = c1.z; bv[7] = c1.w;
    }
#pragma unroll
    for (int i = 0; i < 8; i++) {
        const long row = m0 + ty * 8 + i;
#pragma unroll
        for (int jq = 0; jq < 2; jq++) {
            float4 o;
            o.x = acc[i][jq * 4 + 0];
            o.y = acc[i][jq * 4 + 1];
            o.z = acc[i][jq * 4 + 2];
            o.w = acc[i][jq * 4 + 3];
            if (HAS_BIAS) {
                o.x += bv[jq * 4 + 0];
                o.y += bv[jq * 4 + 1];
                o.z += bv[jq * 4 + 2];
                o.w += bv[jq * 4 + 3];
            }
            *reinterpret_cast<float4*>(&C[row * (long)N + n0 + tx * 8 + jq * 4]) = o;
        }
    }
}

extern "C" void kernel_launch(void* const* d_in, const int* in_sizes, int n_in,
                              void* d_out, int out_size) {
    // metadata order: x [8192,4096], U [4096,256], V [256,4096], bias [4096]
    const float* x    = (const float*)d_in[0];
    const float* U    = (const float*)d_in[1];
    const float* V    = (const float*)d_in[2];
    const float* bias = (const float*)d_in[3];
    float* out = (float*)d_out;

    float* T = nullptr;
    cudaGetSymbolAddress((void**)&T, g_T);

    // Stage 1: T[8192,256] = x[8192,4096] @ V[256,4096]^T
    sgemm_nt<false><<<dim3(256 / 128, 8192 / 128), 256>>>(x, V, nullptr, T,
                                                          /*N=*/256, /*K=*/4096);
    // Stage 2: out[8192,4096] = T[8192,256] @ U[4096,256]^T + bias
    sgemm_nt<true><<<dim3(4096 / 128, 8192 / 128), 256>>>(T, U, bias, out,
                                                          /*N=*/4096, /*K=*/256);
}

// round 3
// speedup vs baseline: 3.5798x; 3.5798x over previous
#include <cuda_runtime.h>
#include <cuda_bf16.h>
#include <cstdint>

using bf16 = __nv_bfloat16;
#define DEV_INLINE __device__ __forceinline__

// ---------------- scratch (device globals; allocation-free) ----------------
__device__ __align__(16) bf16 g_xh[8192u * 4096u];
__device__ __align__(16) bf16 g_xl[8192u * 4096u];
__device__ __align__(16) bf16 g_vh[256u * 4096u];
__device__ __align__(16) bf16 g_vl[256u * 4096u];
__device__ __align__(16) bf16 g_uh[4096u * 256u];
__device__ __align__(16) bf16 g_ul[4096u * 256u];
__device__ __align__(16) bf16 g_th[8192u * 256u];
__device__ __align__(16) bf16 g_tl[8192u * 256u];

// ---------------- PTX helpers ----------------
DEV_INLINE uint32_t smem_u32(const void* p) {
    uint32_t a;
    asm("{ .reg .u64 t; cvta.to.shared.u64 t, %1; cvt.u32.u64 %0, t; }"
        : "=r"(a) : "l"(p));
    return a;
}

#define CP_ASYNC16(dst, src) \
    asm volatile("cp.async.cg.shared.global [%0], [%1], 16;" :: "r"(dst), "l"(src))
#define CP_COMMIT() asm volatile("cp.async.commit_group;" ::: "memory")
#define CP_WAIT1()  asm volatile("cp.async.wait_group 1;" ::: "memory")

#define LDSM4(r, addr) \
    asm volatile("ldmatrix.sync.aligned.m8n8.x4.shared.b16 {%0,%1,%2,%3}, [%4];" \
                 : "=r"((r)[0]), "=r"((r)[1]), "=r"((r)[2]), "=r"((r)[3]) \
                 : "r"(addr))

#define MMA_BF16(d, a, b) \
    asm volatile("mma.sync.aligned.m16n8k16.row.col.f32.bf16.bf16.f32 " \
                 "{%0,%1,%2,%3},{%4,%5,%6,%7},{%8,%9},{%0,%1,%2,%3};" \
                 : "+f"((d)[0]), "+f"((d)[1]), "+f"((d)[2]), "+f"((d)[3]) \
                 : "r"((a)[0]), "r"((a)[1]), "r"((a)[2]), "r"((a)[3]), \
                   "r"((b)[0]), "r"((b)[1]))

// ---------------- split kernel: fp32 -> (hi, lo) bf16 ----------------
__global__ void split_fp32(const float* __restrict__ s, bf16* __restrict__ hi,
                           bf16* __restrict__ lo, int n) {
    int i = (blockIdx.x * 256 + threadIdx.x) * 4;
    if (i >= n) return;
    float4 v = *reinterpret_cast<const float4*>(&s[i]);
    bf16 h0 = __float2bfloat16(v.x), h1 = __float2bfloat16(v.y);
    bf16 h2 = __float2bfloat16(v.z), h3 = __float2bfloat16(v.w);
    bf16 l0 = __float2bfloat16(v.x - __bfloat162float(h0));
    bf16 l1 = __float2bfloat16(v.y - __bfloat162float(h1));
    bf16 l2 = __float2bfloat16(v.z - __bfloat162float(h2));
    bf16 l3 = __float2bfloat16(v.w - __bfloat162float(h3));
    __nv_bfloat162 ph0{h0, h1}, ph1{h2, h3}, pl0{l0, l1}, pl1{l2, l3};
    *reinterpret_cast<__nv_bfloat162*>(&hi[i])     = ph0;
    *reinterpret_cast<__nv_bfloat162*>(&hi[i + 2]) = ph1;
    *reinterpret_cast<__nv_bfloat162*>(&lo[i])     = pl0;
    *reinterpret_cast<__nv_bfloat162*>(&lo[i + 2]) = pl1;
}

// ---------------- HMMA GEMM ----------------
// C[M,N] = Ah@Bh^T + Ah@Bl^T + Al@Bh^T   (NT, both K-major)
// Block 128x128, KT=32, 512 threads = 16 warps (4 M x 4 N), warp tile 32x32.
// EPI==0: write split bf16 (Ch, Cl). EPI==1: write fp32 + bias.
static constexpr int BM = 128, BN = 128, KT = 32;
static constexpr int STRIDE = 40;                     // bf16 elems per smem row (pad)
static constexpr uint32_t TILE_B  = 128u * STRIDE * 2;  // 10240 B
static constexpr uint32_t STAGE_B = 4u * TILE_B;        // Ah, Al, Bh, Bl
static constexpr uint32_t SMEM_SZ = 2u * STAGE_B;       // double buffer: 81920 B

template <int EPI>
__global__ __launch_bounds__(512, 1)
void lr_gemm(const bf16* __restrict__ Ah, const bf16* __restrict__ Al,
             const bf16* __restrict__ Bh, const bf16* __restrict__ Bl,
             int K, int Nout, const float* __restrict__ bias,
             float* __restrict__ Cf, bf16* __restrict__ Ch, bf16* __restrict__ Cl) {
    extern __shared__ __align__(16) char smem[];
    const uint32_t sb = smem_u32(smem);

    const int tid  = threadIdx.x;
    const int lane = tid & 31;
    const int warp = tid >> 5;
    const int wm = warp & 3;        // warp row (M)
    const int wn = warp >> 2;       // warp col (N)
    const int m0 = blockIdx.y * BM;
    const int n0 = blockIdx.x * BN;
    const int nk = K / KT;

    const bf16* Ahb = Ah + (size_t)m0 * K;
    const bf16* Alb = Al + (size_t)m0 * K;
    const bf16* Bhb = Bh + (size_t)n0 * K;
    const bf16* Blb = Bl + (size_t)n0 * K;

    // cp.async mapping: 512 threads x 16B = one 128x32 bf16 tile per pass
    const int prow = tid >> 2;               // 0..127
    const int pke  = (tid & 3) * 8;          // k element offset of 16B chunk
    const uint32_t pdst = (uint32_t)(prow * STRIDE + pke) * 2;

    auto produce = [&](int j) {
        if (j < nk) {
            const uint32_t st = sb + (uint32_t)(j & 1) * STAGE_B;
            const size_t go = (size_t)prow * K + j * KT + pke;
            CP_ASYNC16(st + 0 * TILE_B + pdst, Ahb + go);
            CP_ASYNC16(st + 1 * TILE_B + pdst, Alb + go);
            CP_ASYNC16(st + 2 * TILE_B + pdst, Bhb + go);
            CP_ASYNC16(st + 3 * TILE_B + pdst, Blb + go);
        }
        CP_COMMIT();
    };

    float acc[2][4][4];
#pragma unroll
    for (int mt = 0; mt < 2; mt++)
#pragma unroll
        for (int nt = 0; nt < 4; nt++)
#pragma unroll
            for (int e = 0; e < 4; e++) acc[mt][nt][e] = 0.0f;

    // ldmatrix lane offsets (bytes within a tile)
    const int lr = lane & 7, lm = lane >> 3;
    // A x4 mats: (m0,k0),(m8,k0),(m0,k8),(m8,k8)
    const uint32_t offA = (uint32_t)(((lm & 1) * 8 + lr) * STRIDE + (lm >> 1) * 8) * 2;
    // B x4 mats: (n0,k0),(n0,k8),(n8,k0),(n8,k8)
    const uint32_t offB = (uint32_t)(((lm >> 1) * 8 + lr) * STRIDE + (lm & 1) * 8) * 2;
    const uint32_t rowA = (uint32_t)(wm * 32) * STRIDE * 2;
    const uint32_t rowB = (uint32_t)(wn * 32) * STRIDE * 2;

    produce(0);
    for (int i = 0; i < nk; i++) {
        produce(i + 1);
        CP_WAIT1();
        __syncthreads();
        const uint32_t st = sb + (uint32_t)(i & 1) * STAGE_B;
        const uint32_t aH = st + 0 * TILE_B + rowA + offA;
        const uint32_t aL = st + 1 * TILE_B + rowA + offA;
        const uint32_t bH = st + 2 * TILE_B + rowB + offB;
        const uint32_t bL = st + 3 * TILE_B + rowB + offB;
#pragma unroll
        for (int ks = 0; ks < 2; ks++) {
            const uint32_t kb = (uint32_t)ks * 16 * 2;
            uint32_t ah[2][4], al[2][4], bh[8], bl[8];
            LDSM4(ah[0], aH + kb);
            LDSM4(ah[1], aH + kb + 16u * STRIDE * 2);
            LDSM4(al[0], aL + kb);
            LDSM4(al[1], aL + kb + 16u * STRIDE * 2);
            LDSM4(&bh[0], bH + kb);
            LDSM4(&bh[4], bH + kb + 16u * STRIDE * 2);
            LDSM4(&bl[0], bL + kb);
            LDSM4(&bl[4], bL + kb + 16u * STRIDE * 2);
#pragma unroll
            for (int mt = 0; mt < 2; mt++)
#pragma unroll
                for (int nt = 0; nt < 4; nt++) {
                    MMA_BF16(acc[mt][nt], ah[mt], (&bh[nt * 2]));
                    MMA_BF16(acc[mt][nt], ah[mt], (&bl[nt * 2]));
                    MMA_BF16(acc[mt][nt], al[mt], (&bh[nt * 2]));
                }
        }
        __syncthreads();
    }

    // ---------------- epilogue ----------------
    const int er = lane >> 2;             // 0..7
    const int ec = (lane & 3) * 2;        // 0,2,4,6
#pragma unroll
    for (int nt = 0; nt < 4; nt++) {
        const int col = n0 + wn * 32 + nt * 8 + ec;
        float b0 = 0.f, b1 = 0.f;
        if (EPI == 1) { b0 = bias[col]; b1 = bias[col + 1]; }
#pragma unroll
        for (int mt = 0; mt < 2; mt++) {
            const int r0g = m0 + wm * 32 + mt * 16 + er;
#pragma unroll
            for (int h = 0; h < 2; h++) {   // row halves: +0, +8
                const int row = r0g + h * 8;
                const float v0 = acc[mt][nt][h * 2 + 0];
                const float v1 = acc[mt][nt][h * 2 + 1];
                if (EPI == 1) {
                    float2 o = make_float2(v0 + b0, v1 + b1);
                    *reinterpret_cast<float2*>(&Cf[(size_t)row * Nout + col]) = o;
                } else {
                    bf16 h0 = __float2bfloat16(v0), h1 = __float2bfloat16(v1);
                    bf16 l0 = __float2bfloat16(v0 - __bfloat162float(h0));
                    bf16 l1 = __float2bfloat16(v1 - __bfloat162float(h1));
                    __nv_bfloat162 ph{h0, h1}, pl{l0, l1};
                    const size_t idx = (size_t)row * Nout + col;
                    *reinterpret_cast<__nv_bfloat162*>(&Ch[idx]) = ph;
                    *reinterpret_cast<__nv_bfloat162*>(&Cl[idx]) = pl;
                }
            }
        }
    }
}

// ---------------- launch ----------------
extern "C" void kernel_launch(void* const* d_in, const int* in_sizes, int n_in,
                              void* d_out, int out_size) {
    const float* x    = (const float*)d_in[0];   // [8192, 4096]
    const float* U    = (const float*)d_in[1];   // [4096, 256]
    const float* V    = (const float*)d_in[2];   // [256, 4096]
    const float* bias = (const float*)d_in[3];   // [4096]
    float* out = (float*)d_out;                  // [8192, 4096]

    bf16 *xh, *xl, *vh, *vl, *uh, *ul, *th, *tl;
    cudaGetSymbolAddress((void**)&xh, g_xh);
    cudaGetSymbolAddress((void**)&xl, g_xl);
    cudaGetSymbolAddress((void**)&vh, g_vh);
    cudaGetSymbolAddress((void**)&vl, g_vl);
    cudaGetSymbolAddress((void**)&uh, g_uh);
    cudaGetSymbolAddress((void**)&ul, g_ul);
    cudaGetSymbolAddress((void**)&th, g_th);
    cudaGetSymbolAddress((void**)&tl, g_tl);

    cudaFuncSetAttribute(lr_gemm<0>, cudaFuncAttributeMaxDynamicSharedMemorySize, SMEM_SZ);
    cudaFuncSetAttribute(lr_gemm<1>, cudaFuncAttributeMaxDynamicSharedMemorySize, SMEM_SZ);

    // splits
    split_fp32<<<(8192 * 4096 / 4) / 256, 256>>>(x, xh, xl, 8192 * 4096);
    split_fp32<<<(256 * 4096 / 4) / 256, 256>>>(V, vh, vl, 256 * 4096);
    split_fp32<<<(4096 * 256 / 4) / 256, 256>>>(U, uh, ul, 4096 * 256);

    // Stage 1: T[8192,256] = x @ V^T (K=4096) -> split bf16 T
    lr_gemm<0><<<dim3(256 / 128, 8192 / 128), 512, SMEM_SZ>>>(
        xh, xl, vh, vl, 4096, 256, nullptr, nullptr, th, tl);

    // Stage 2: out[8192,4096] = T @ U^T + bias (K=256)
    lr_gemm<1><<<dim3(4096 / 128, 8192 / 128), 512, SMEM_SZ>>>(
        th, tl, uh, ul, 256, 4096, bias, out, nullptr, nullptr);
}

// round 4
// speedup vs baseline: 3.5960x; 1.0045x over previous
#include <cuda_runtime.h>
#include <cuda_bf16.h>
#include <cstdint>

using bf16 = __nv_bfloat16;
#define DEV_INLINE __device__ __forceinline__

// ---------------- scratch (device globals; allocation-free) ----------------
__device__ __align__(16) bf16 g_xh[8192u * 4096u];
__device__ __align__(16) bf16 g_xl[8192u * 4096u];
__device__ __align__(16) bf16 g_vh[256u * 4096u];
__device__ __align__(16) bf16 g_vl[256u * 4096u];
__device__ __align__(16) bf16 g_uh[4096u * 256u];
__device__ __align__(16) bf16 g_ul[4096u * 256u];
__device__ __align__(16) bf16 g_th[8192u * 256u];
__device__ __align__(16) bf16 g_tl[8192u * 256u];

// ---------------- PTX helpers ----------------
DEV_INLINE uint32_t smem_u32(const void* p) {
    uint32_t a;
    asm("{ .reg .u64 t; cvta.to.shared.u64 t, %1; cvt.u32.u64 %0, t; }"
        : "=r"(a) : "l"(p));
    return a;
}

#define CP_ASYNC16(dst, src) \
    asm volatile("cp.async.cg.shared.global [%0], [%1], 16;" :: "r"(dst), "l"(src))
#define CP_COMMIT() asm volatile("cp.async.commit_group;" ::: "memory")
#define CP_WAIT1()  asm volatile("cp.async.wait_group 1;" ::: "memory")

#define LDSM4(r, addr) \
    asm volatile("ldmatrix.sync.aligned.m8n8.x4.shared.b16 {%0,%1,%2,%3}, [%4];" \
                 : "=r"((r)[0]), "=r"((r)[1]), "=r"((r)[2]), "=r"((r)[3]) \
                 : "r"(addr))

#define MMA_BF16(d, a, b) \
    asm volatile("mma.sync.aligned.m16n8k16.row.col.f32.bf16.bf16.f32 " \
                 "{%0,%1,%2,%3},{%4,%5,%6,%7},{%8,%9},{%0,%1,%2,%3};" \
                 : "+f"((d)[0]), "+f"((d)[1]), "+f"((d)[2]), "+f"((d)[3]) \
                 : "r"((a)[0]), "r"((a)[1]), "r"((a)[2]), "r"((a)[3]), \
                   "r"((b)[0]), "r"((b)[1]))

// ---------------- split kernel: fp32 -> (hi, lo) bf16 ----------------
__global__ void split_fp32(const float* __restrict__ s, bf16* __restrict__ hi,
                           bf16* __restrict__ lo, int n) {
    int i = (blockIdx.x * 256 + threadIdx.x) * 4;
    if (i >= n) return;
    float4 v = *reinterpret_cast<const float4*>(&s[i]);
    bf16 h0 = __float2bfloat16(v.x), h1 = __float2bfloat16(v.y);
    bf16 h2 = __float2bfloat16(v.z), h3 = __float2bfloat16(v.w);
    bf16 l0 = __float2bfloat16(v.x - __bfloat162float(h0));
    bf16 l1 = __float2bfloat16(v.y - __bfloat162float(h1));
    bf16 l2 = __float2bfloat16(v.z - __bfloat162float(h2));
    bf16 l3 = __float2bfloat16(v.w - __bfloat162float(h3));
    __nv_bfloat162 ph0{h0, h1}, ph1{h2, h3}, pl0{l0, l1}, pl1{l2, l3};
    *reinterpret_cast<__nv_bfloat162*>(&hi[i])     = ph0;
    *reinterpret_cast<__nv_bfloat162*>(&hi[i + 2]) = ph1;
    *reinterpret_cast<__nv_bfloat162*>(&lo[i])     = pl0;
    *reinterpret_cast<__nv_bfloat162*>(&lo[i + 2]) = pl1;
}

// ---------------- HMMA GEMM ----------------
// C[M,N] = Ah@Bh^T + Ah@Bl^T + Al@Bh^T   (NT, both K-major)
// Block 128x128, KT=32, 512 threads = 16 warps (4 M x 4 N), warp tile 32x32.
// 3-stage cp.async ring, 1 sync/iter, term-major MMA issue (RAW chains broken).
static constexpr int BM = 128, BN = 128, KT = 32;
static constexpr int NST = 3;
static constexpr int STRIDE = 40;                       // bf16 elems per smem row (pad)
static constexpr uint32_t TILE_B  = 128u * STRIDE * 2;  // 10240 B
static constexpr uint32_t STAGE_B = 4u * TILE_B;        // Ah, Al, Bh, Bl
static constexpr uint32_t SMEM_SZ = NST * STAGE_B;      // 122880 B

template <int EPI>
__global__ __launch_bounds__(512, 1)
void lr_gemm(const bf16* __restrict__ Ah, const bf16* __restrict__ Al,
             const bf16* __restrict__ Bh, const bf16* __restrict__ Bl,
             int K, int Nout, const float* __restrict__ bias,
             float* __restrict__ Cf, bf16* __restrict__ Ch, bf16* __restrict__ Cl) {
    extern __shared__ __align__(16) char smem[];
    const uint32_t sb = smem_u32(smem);

    const int tid  = threadIdx.x;
    const int lane = tid & 31;
    const int warp = tid >> 5;
    const int wm = warp & 3;        // warp row (M)
    const int wn = warp >> 2;       // warp col (N)
    const int m0 = blockIdx.y * BM;
    const int n0 = blockIdx.x * BN;
    const int nk = K / KT;

    const bf16* Ahb = Ah + (size_t)m0 * K;
    const bf16* Alb = Al + (size_t)m0 * K;
    const bf16* Bhb = Bh + (size_t)n0 * K;
    const bf16* Blb = Bl + (size_t)n0 * K;

    // cp.async mapping: 512 threads x 16B = one 128x32 bf16 tile per pass
    const int prow = tid >> 2;               // 0..127
    const int pke  = (tid & 3) * 8;          // k element offset of 16B chunk
    const uint32_t pdst = (uint32_t)(prow * STRIDE + pke) * 2;

    auto produce = [&](int j) {
        if (j < nk) {
            const uint32_t st = sb + (uint32_t)(j % NST) * STAGE_B;
            const size_t go = (size_t)prow * K + j * KT + pke;
            CP_ASYNC16(st + 0 * TILE_B + pdst, Ahb + go);
            CP_ASYNC16(st + 1 * TILE_B + pdst, Alb + go);
            CP_ASYNC16(st + 2 * TILE_B + pdst, Bhb + go);
            CP_ASYNC16(st + 3 * TILE_B + pdst, Blb + go);
        }
        CP_COMMIT();
    };

    float acc[2][4][4];
#pragma unroll
    for (int mt = 0; mt < 2; mt++)
#pragma unroll
        for (int nt = 0; nt < 4; nt++)
#pragma unroll
            for (int e = 0; e < 4; e++) acc[mt][nt][e] = 0.0f;

    // ldmatrix lane offsets (bytes within a tile)
    const int lr = lane & 7, lm = lane >> 3;
    // A x4 mats: (m0,k0),(m8,k0),(m0,k8),(m8,k8)
    const uint32_t offA = (uint32_t)(((lm & 1) * 8 + lr) * STRIDE + (lm >> 1) * 8) * 2;
    // B x4 mats: (n0,k0),(n0,k8),(n8,k0),(n8,k8)
    const uint32_t offB = (uint32_t)(((lm >> 1) * 8 + lr) * STRIDE + (lm & 1) * 8) * 2;
    const uint32_t rowA = (uint32_t)(wm * 32) * STRIDE * 2;
    const uint32_t rowB = (uint32_t)(wn * 32) * STRIDE * 2;

    // prologue: fill 2 of 3 ring stages
    produce(0);
    produce(1);

    for (int i = 0; i < nk; i++) {
        CP_WAIT1();            // group i complete (<=1 pending: i+1)
        __syncthreads();       // all threads done computing iter i-1 (stage (i-1)%3)
        produce(i + 2);        // overwrite stage (i+2)%3 == (i-1)%3 — safe now
        const uint32_t st = sb + (uint32_t)(i % NST) * STAGE_B;
        const uint32_t aH = st + 0 * TILE_B + rowA + offA;
        const uint32_t aL = st + 1 * TILE_B + rowA + offA;
        const uint32_t bH = st + 2 * TILE_B + rowB + offB;
        const uint32_t bL = st + 3 * TILE_B + rowB + offB;
#pragma unroll
        for (int ks = 0; ks < 2; ks++) {
            const uint32_t kb = (uint32_t)ks * 16 * 2;
            uint32_t ah[2][4], al[2][4], bh[8], bl[8];
            LDSM4(ah[0], aH + kb);
            LDSM4(ah[1], aH + kb + 16u * STRIDE * 2);
            LDSM4(al[0], aL + kb);
            LDSM4(al[1], aL + kb + 16u * STRIDE * 2);
            LDSM4(&bh[0], bH + kb);
            LDSM4(&bh[4], bH + kb + 16u * STRIDE * 2);
            LDSM4(&bl[0], bL + kb);
            LDSM4(&bl[4], bL + kb + 16u * STRIDE * 2);
            // term-major: dependent MMAs on the same acc are 8 issues apart
#pragma unroll
            for (int mt = 0; mt < 2; mt++)
#pragma unroll
                for (int nt = 0; nt < 4; nt++)
                    MMA_BF16(acc[mt][nt], ah[mt], (&bh[nt * 2]));
#pragma unroll
            for (int mt = 0; mt < 2; mt++)
#pragma unroll
                for (int nt = 0; nt < 4; nt++)
                    MMA_BF16(acc[mt][nt], ah[mt], (&bl[nt * 2]));
#pragma unroll
            for (int mt = 0; mt < 2; mt++)
#pragma unroll
                for (int nt = 0; nt < 4; nt++)
                    MMA_BF16(acc[mt][nt], al[mt], (&bh[nt * 2]));
        }
    }

    // ---------------- epilogue ----------------
    const int er = lane >> 2;             // 0..7
    const int ec = (lane & 3) * 2;        // 0,2,4,6
#pragma unroll
    for (int nt = 0; nt < 4; nt++) {
        const int col = n0 + wn * 32 + nt * 8 + ec;
        float b0 = 0.f, b1 = 0.f;
        if (EPI == 1) { b0 = bias[col]; b1 = bias[col + 1]; }
#pragma unroll
        for (int mt = 0; mt < 2; mt++) {
            const int r0g = m0 + wm * 32 + mt * 16 + er;
#pragma unroll
            for (int h = 0; h < 2; h++) {   // row halves: +0, +8
                const int row = r0g + h * 8;
                const float v0 = acc[mt][nt][h * 2 + 0];
                const float v1 = acc[mt][nt][h * 2 + 1];
                if (EPI == 1) {
                    float2 o = make_float2(v0 + b0, v1 + b1);
                    *reinterpret_cast<float2*>(&Cf[(size_t)row * Nout + col]) = o;
                } else {
                    bf16 h0 = __float2bfloat16(v0), h1 = __float2bfloat16(v1);
                    bf16 l0 = __float2bfloat16(v0 - __bfloat162float(h0));
                    bf16 l1 = __float2bfloat16(v1 - __bfloat162float(h1));
                    __nv_bfloat162 ph{h0, h1}, pl{l0, l1};
                    const size_t idx = (size_t)row * Nout + col;
                    *reinterpret_cast<__nv_bfloat162*>(&Ch[idx]) = ph;
                    *reinterpret_cast<__nv_bfloat162*>(&Cl[idx]) = pl;
                }
            }
        }
    }
}

// ---------------- launch ----------------
extern "C" void kernel_launch(void* const* d_in, const int* in_sizes, int n_in,
                              void* d_out, int out_size) {
    const float* x    = (const float*)d_in[0];   // [8192, 4096]
    const float* U    = (const float*)d_in[1];   // [4096, 256]
    const float* V    = (const float*)d_in[2];   // [256, 4096]
    const float* bias = (const float*)d_in[3];   // [4096]
    float* out = (float*)d_out;                  // [8192, 4096]

    bf16 *xh, *xl, *vh, *vl, *uh, *ul, *th, *tl;
    cudaGetSymbolAddress((void**)&xh, g_xh);
    cudaGetSymbolAddress((void**)&xl, g_xl);
    cudaGetSymbolAddress((void**)&vh, g_vh);
    cudaGetSymbolAddress((void**)&vl, g_vl);
    cudaGetSymbolAddress((void**)&uh, g_uh);
    cudaGetSymbolAddress((void**)&ul, g_ul);
    cudaGetSymbolAddress((void**)&th, g_th);
    cudaGetSymbolAddress((void**)&tl, g_tl);

    cudaFuncSetAttribute(lr_gemm<0>, cudaFuncAttributeMaxDynamicSharedMemorySize, SMEM_SZ);
    cudaFuncSetAttribute(lr_gemm<1>, cudaFuncAttributeMaxDynamicSharedMemorySize, SMEM_SZ);

    // splits
    split_fp32<<<(8192 * 4096 / 4) / 256, 256>>>(x, xh, xl, 8192 * 4096);
    split_fp32<<<(256 * 4096 / 4) / 256, 256>>>(V, vh, vl, 256 * 4096);
    split_fp32<<<(4096 * 256 / 4) / 256, 256>>>(U, uh, ul, 4096 * 256);

    // Stage 1: T[8192,256] = x @ V^T (K=4096) -> split bf16 T
    lr_gemm<0><<<dim3(256 / 128, 8192 / 128), 512, SMEM_SZ>>>(
        xh, xl, vh, vl, 4096, 256, nullptr, nullptr, th, tl);

    // Stage 2: out[8192,4096] = T @ U^T + bias (K=256)
    lr_gemm<1><<<dim3(4096 / 128, 8192 / 128), 512, SMEM_SZ>>>(
        th, tl, uh, ul, 256, 4096, bias, out, nullptr, nullptr);
}

// round 5
// speedup vs baseline: 4.1344x; 1.1497x over previous
#include <cuda_runtime.h>
#include <cuda_bf16.h>
#include <cstdint>

using bf16 = __nv_bfloat16;
#define DEV_INLINE __device__ __forceinline__

// ---------------- scratch (device globals; allocation-free) ----------------
__device__ __align__(16) bf16 g_vh[256u * 4096u];
__device__ __align__(16) bf16 g_vl[256u * 4096u];
__device__ __align__(16) bf16 g_uh[4096u * 256u];
__device__ __align__(16) bf16 g_ul[4096u * 256u];
__device__ __align__(16) bf16 g_th[8192u * 256u];
__device__ __align__(16) bf16 g_tl[8192u * 256u];

// ---------------- PTX helpers ----------------
DEV_INLINE uint32_t smem_u32(const void* p) {
    uint32_t a;
    asm("{ .reg .u64 t; cvta.to.shared.u64 t, %1; cvt.u32.u64 %0, t; }"
        : "=r"(a) : "l"(p));
    return a;
}

#define CP_ASYNC16(dst, src) \
    asm volatile("cp.async.cg.shared.global [%0], [%1], 16;" :: "r"(dst), "l"(src))
#define CP_COMMIT() asm volatile("cp.async.commit_group;" ::: "memory")
#define CP_WAIT1()  asm volatile("cp.async.wait_group 1;" ::: "memory")

#define LDSM4(r, addr) \
    asm volatile("ldmatrix.sync.aligned.m8n8.x4.shared.b16 {%0,%1,%2,%3}, [%4];" \
                 : "=r"((r)[0]), "=r"((r)[1]), "=r"((r)[2]), "=r"((r)[3]) \
                 : "r"(addr))

#define MMA_BF16(d, a, b) \
    asm volatile("mma.sync.aligned.m16n8k16.row.col.f32.bf16.bf16.f32 " \
                 "{%0,%1,%2,%3},{%4,%5,%6,%7},{%8,%9},{%0,%1,%2,%3};" \
                 : "+f"((d)[0]), "+f"((d)[1]), "+f"((d)[2]), "+f"((d)[3]) \
                 : "r"((a)[0]), "r"((a)[1]), "r"((a)[2]), "r"((a)[3]), \
                   "r"((b)[0]), "r"((b)[1]))

DEV_INLINE void split1(float v, bf16& h, bf16& l) {
    h = __float2bfloat16(v);
    l = __float2bfloat16(v - __bfloat162float(h));
}

// ---------------- tiling constants ----------------
static constexpr int BM = 128, BN = 128, KT = 32;
static constexpr int NST = 3;
static constexpr int STRIDE = 40;                       // bf16 elems per smem row (pad)
static constexpr uint32_t TILE_B  = 128u * STRIDE * 2;  // 10240 B
static constexpr uint32_t STAGE_B = 4u * TILE_B;        // Ah, Al, Bh, Bl
static constexpr uint32_t SMEM_SZ = NST * STAGE_B;      // 122880 B

// ---------------- fused split kernel for V and U ----------------
__global__ void split_vu(const float* __restrict__ V, bf16* __restrict__ vh,
                         bf16* __restrict__ vl, const float* __restrict__ U,
                         bf16* __restrict__ uh, bf16* __restrict__ ul, int n1) {
    int i = (blockIdx.x * 256 + threadIdx.x) * 4;
    const float* s; bf16 *hi, *lo;
    if (i < n1) { s = V; hi = vh; lo = vl; }
    else        { s = U; hi = uh; lo = ul; i -= n1; }
    float4 v = *reinterpret_cast<const float4*>(&s[i]);
    bf16 h0, h1, h2, h3, l0, l1, l2, l3;
    split1(v.x, h0, l0); split1(v.y, h1, l1);
    split1(v.z, h2, l2); split1(v.w, h3, l3);
    __nv_bfloat162 ph0{h0, h1}, ph1{h2, h3}, pl0{l0, l1}, pl1{l2, l3};
    *reinterpret_cast<__nv_bfloat162*>(&hi[i])     = ph0;
    *reinterpret_cast<__nv_bfloat162*>(&hi[i + 2]) = ph1;
    *reinterpret_cast<__nv_bfloat162*>(&lo[i])     = pl0;
    *reinterpret_cast<__nv_bfloat162*>(&lo[i + 2]) = pl1;
}

// ---------------- shared MMA consumer ----------------
// computes 48 MMAs on stage `st`, accumulating into acc
DEV_INLINE void consume_stage(uint32_t st, uint32_t rowA, uint32_t rowB,
                              uint32_t offA, uint32_t offB, float acc[2][4][4]) {
    const uint32_t aH = st + 0 * TILE_B + rowA + offA;
    const uint32_t aL = st + 1 * TILE_B + rowA + offA;
    const uint32_t bH = st + 2 * TILE_B + rowB + offB;
    const uint32_t bL = st + 3 * TILE_B + rowB + offB;
#pragma unroll
    for (int ks = 0; ks < 2; ks++) {
        const uint32_t kb = (uint32_t)ks * 16 * 2;
        uint32_t ah[2][4], al[2][4], bh[8], bl[8];
        LDSM4(ah[0], aH + kb);
        LDSM4(ah[1], aH + kb + 16u * STRIDE * 2);
        LDSM4(al[0], aL + kb);
        LDSM4(al[1], aL + kb + 16u * STRIDE * 2);
        LDSM4(&bh[0], bH + kb);
        LDSM4(&bh[4], bH + kb + 16u * STRIDE * 2);
        LDSM4(&bl[0], bL + kb);
        LDSM4(&bl[4], bL + kb + 16u * STRIDE * 2);
#pragma unroll
        for (int mt = 0; mt < 2; mt++)
#pragma unroll
            for (int nt = 0; nt < 4; nt++) {
                MMA_BF16(acc[mt][nt], ah[mt], (&bh[nt * 2]));
                MMA_BF16(acc[mt][nt], ah[mt], (&bl[nt * 2]));
                MMA_BF16(acc[mt][nt], al[mt], (&bh[nt * 2]));
            }
    }
}

// ---------------- Stage 1: T = x @ V^T, x fp32 (split fused in-kernel) ----------------
__global__ __launch_bounds__(512, 1)
void lr_gemm_s1(const float* __restrict__ X,
                const bf16* __restrict__ Bh, const bf16* __restrict__ Bl,
                int K, int Nout, bf16* __restrict__ Ch, bf16* __restrict__ Cl) {
    extern __shared__ __align__(16) char smem[];
    const uint32_t sb = smem_u32(smem);

    const int tid  = threadIdx.x;
    const int lane = tid & 31;
    const int warp = tid >> 5;
    const int wm = warp & 3, wn = warp >> 2;
    const int m0 = blockIdx.y * BM;
    const int n0 = blockIdx.x * BN;
    const int nk = K / KT;

    const float* Xb  = X  + (size_t)m0 * K;
    const bf16*  Bhb = Bh + (size_t)n0 * K;
    const bf16*  Blb = Bl + (size_t)n0 * K;

    const int prow = tid >> 2;            // 0..127
    const int pke  = (tid & 3) * 8;       // 0,8,16,24
    const uint32_t pdst = (uint32_t)(prow * STRIDE + pke) * 2;  // bytes

    auto produceB = [&](int j) {
        if (j < nk) {
            const uint32_t st = sb + (uint32_t)(j % NST) * STAGE_B;
            const size_t go = (size_t)prow * K + j * KT + pke;
            CP_ASYNC16(st + 2 * TILE_B + pdst, Bhb + go);
            CP_ASYNC16(st + 3 * TILE_B + pdst, Blb + go);
        }
        CP_COMMIT();
    };

    float ra[8];
    auto loadA = [&](int j) {
        if (j < nk) {
            const float* p = Xb + (size_t)prow * K + j * KT + pke;
            float4 v0 = *reinterpret_cast<const float4*>(p);
            float4 v1 = *reinterpret_cast<const float4*>(p + 4);
            ra[0] = v0.x; ra[1] = v0.y; ra[2] = v0.z; ra[3] = v0.w;
            ra[4] = v1.x; ra[5] = v1.y; ra[6] = v1.z; ra[7] = v1.w;
        }
    };
    auto stsA = [&](int j) {
        const uint32_t st = sb + (uint32_t)(j % NST) * STAGE_B;
        bf16 h[8], l[8];
#pragma unroll
        for (int e = 0; e < 8; e++) split1(ra[e], h[e], l[e]);
        uint4 vh4, vl4;
        __nv_bfloat162 t;
        t = {h[0], h[1]}; vh4.x = *reinterpret_cast<uint32_t*>(&t);
        t = {h[2], h[3]}; vh4.y = *reinterpret_cast<uint32_t*>(&t);
        t = {h[4], h[5]}; vh4.z = *reinterpret_cast<uint32_t*>(&t);
        t = {h[6], h[7]}; vh4.w = *reinterpret_cast<uint32_t*>(&t);
        t = {l[0], l[1]}; vl4.x = *reinterpret_cast<uint32_t*>(&t);
        t = {l[2], l[3]}; vl4.y = *reinterpret_cast<uint32_t*>(&t);
        t = {l[4], l[5]}; vl4.z = *reinterpret_cast<uint32_t*>(&t);
        t = {l[6], l[7]}; vl4.w = *reinterpret_cast<uint32_t*>(&t);
        *reinterpret_cast<uint4*>(smem + (st - sb) + 0 * TILE_B + pdst) = vh4;
        *reinterpret_cast<uint4*>(smem + (st - sb) + 1 * TILE_B + pdst) = vl4;
    };

    float acc[2][4][4];
#pragma unroll
    for (int mt = 0; mt < 2; mt++)
#pragma unroll
        for (int nt = 0; nt < 4; nt++)
#pragma unroll
            for (int e = 0; e < 4; e++) acc[mt][nt][e] = 0.0f;

    const int lr = lane & 7, lm = lane >> 3;
    const uint32_t offA = (uint32_t)(((lm & 1) * 8 + lr) * STRIDE + (lm >> 1) * 8) * 2;
    const uint32_t offB = (uint32_t)(((lm >> 1) * 8 + lr) * STRIDE + (lm & 1) * 8) * 2;
    const uint32_t rowA = (uint32_t)(wm * 32) * STRIDE * 2;
    const uint32_t rowB = (uint32_t)(wn * 32) * STRIDE * 2;

    loadA(0);
    produceB(0);
    produceB(1);

    for (int i = 0; i < nk; i++) {
        stsA(i);               // A(i) regs -> stage i%3 (visible after sync below)
        loadA(i + 1);          // prefetch next A tile into regs
        CP_WAIT1();            // B group i complete
        __syncthreads();       // A STS + B tiles visible; stage (i-1)%3 free
        produceB(i + 2);
        consume_stage(sb + (uint32_t)(i % NST) * STAGE_B, rowA, rowB, offA, offB, acc);
    }

    // epilogue: write split bf16 T
    const int er = lane >> 2, ec = (lane & 3) * 2;
#pragma unroll
    for (int nt = 0; nt < 4; nt++) {
        const int col = n0 + wn * 32 + nt * 8 + ec;
#pragma unroll
        for (int mt = 0; mt < 2; mt++) {
            const int r0g = m0 + wm * 32 + mt * 16 + er;
#pragma unroll
            for (int h = 0; h < 2; h++) {
                const int row = r0g + h * 8;
                bf16 h0, h1, l0, l1;
                split1(acc[mt][nt][h * 2 + 0], h0, l0);
                split1(acc[mt][nt][h * 2 + 1], h1, l1);
                __nv_bfloat162 ph{h0, h1}, pl{l0, l1};
                const size_t idx = (size_t)row * Nout + col;
                *reinterpret_cast<__nv_bfloat162*>(&Ch[idx]) = ph;
                *reinterpret_cast<__nv_bfloat162*>(&Cl[idx]) = pl;
            }
        }
    }
}

// ---------------- Stage 2: out = T @ U^T + bias (all-bf16 operands) ----------------
__global__ __launch_bounds__(512, 1)
void lr_gemm_s2(const bf16* __restrict__ Ah, const bf16* __restrict__ Al,
                const bf16* __restrict__ Bh, const bf16* __restrict__ Bl,
                int K, int Nout, const float* __restrict__ bias,
                float* __restrict__ Cf) {
    extern __shared__ __align__(16) char smem[];
    const uint32_t sb = smem_u32(smem);

    const int tid  = threadIdx.x;
    const int lane = tid & 31;
    const int warp = tid >> 5;
    const int wm = warp & 3, wn = warp >> 2;
    const int m0 = blockIdx.y * BM;
    const int n0 = blockIdx.x * BN;
    const int nk = K / KT;

    const bf16* Ahb = Ah + (size_t)m0 * K;
    const bf16* Alb = Al + (size_t)m0 * K;
    const bf16* Bhb = Bh + (size_t)n0 * K;
    const bf16* Blb = Bl + (size_t)n0 * K;

    const int prow = tid >> 2;
    const int pke  = (tid & 3) * 8;
    const uint32_t pdst = (uint32_t)(prow * STRIDE + pke) * 2;

    auto produce = [&](int j) {
        if (j < nk) {
            const uint32_t st = sb + (uint32_t)(j % NST) * STAGE_B;
            const size_t go = (size_t)prow * K + j * KT + pke;
            CP_ASYNC16(st + 0 * TILE_B + pdst, Ahb + go);
            CP_ASYNC16(st + 1 * TILE_B + pdst, Alb + go);
            CP_ASYNC16(st + 2 * TILE_B + pdst, Bhb + go);
            CP_ASYNC16(st + 3 * TILE_B + pdst, Blb + go);
        }
        CP_COMMIT();
    };

    float acc[2][4][4];
#pragma unroll
    for (int mt = 0; mt < 2; mt++)
#pragma unroll
        for (int nt = 0; nt < 4; nt++)
#pragma unroll
            for (int e = 0; e < 4; e++) acc[mt][nt][e] = 0.0f;

    const int lr = lane & 7, lm = lane >> 3;
    const uint32_t offA = (uint32_t)(((lm & 1) * 8 + lr) * STRIDE + (lm >> 1) * 8) * 2;
    const uint32_t offB = (uint32_t)(((lm >> 1) * 8 + lr) * STRIDE + (lm & 1) * 8) * 2;
    const uint32_t rowA = (uint32_t)(wm * 32) * STRIDE * 2;
    const uint32_t rowB = (uint32_t)(wn * 32) * STRIDE * 2;

    produce(0);
    produce(1);

    for (int i = 0; i < nk; i++) {
        CP_WAIT1();
        __syncthreads();
        produce(i + 2);
        consume_stage(sb + (uint32_t)(i % NST) * STAGE_B, rowA, rowB, offA, offB, acc);
    }

    const int er = lane >> 2, ec = (lane & 3) * 2;
#pragma unroll
    for (int nt = 0; nt < 4; nt++) {
        const int col = n0 + wn * 32 + nt * 8 + ec;
        const float b0 = bias[col], b1 = bias[col + 1];
#pragma unroll
        for (int mt = 0; mt < 2; mt++) {
            const int r0g = m0 + wm * 32 + mt * 16 + er;
#pragma unroll
            for (int h = 0; h < 2; h++) {
                const int row = r0g + h * 8;
                float2 o = make_float2(acc[mt][nt][h * 2 + 0] + b0,
                                       acc[mt][nt][h * 2 + 1] + b1);
                *reinterpret_cast<float2*>(&Cf[(size_t)row * Nout + col]) = o;
            }
        }
    }
}

// ---------------- launch ----------------
extern "C" void kernel_launch(void* const* d_in, const int* in_sizes, int n_in,
                              void* d_out, int out_size) {
    const float* x    = (const float*)d_in[0];   // [8192, 4096]
    const float* U    = (const float*)d_in[1];   // [4096, 256]
    const float* V    = (const float*)d_in[2];   // [256, 4096]
    const float* bias = (const float*)d_in[3];   // [4096]
    float* out = (float*)d_out;                  // [8192, 4096]

    bf16 *vh, *vl, *uh, *ul, *th, *tl;
    cudaGetSymbolAddress((void**)&vh, g_vh);
    cudaGetSymbolAddress((void**)&vl, g_vl);
    cudaGetSymbolAddress((void**)&uh, g_uh);
    cudaGetSymbolAddress((void**)&ul, g_ul);
    cudaGetSymbolAddress((void**)&th, g_th);
    cudaGetSymbolAddress((void**)&tl, g_tl);

    cudaFuncSetAttribute(lr_gemm_s1, cudaFuncAttributeMaxDynamicSharedMemorySize, SMEM_SZ);
    cudaFuncSetAttribute(lr_gemm_s2, cudaFuncAttributeMaxDynamicSharedMemorySize, SMEM_SZ);

    // split V and U in one launch (1M elems each)
    const int n1 = 256 * 4096;
    split_vu<<<(2 * n1 / 4) / 256, 256>>>(V, vh, vl, U, uh, ul, n1);

    // Stage 1: T[8192,256] = x @ V^T (K=4096), x split fused in-kernel
    lr_gemm_s1<<<dim3(256 / 128, 8192 / 128), 512, SMEM_SZ>>>(
        x, vh, vl, 4096, 256, th, tl);

    // Stage 2: out[8192,4096] = T @ U^T + bias (K=256)
    lr_gemm_s2<<<dim3(4096 / 128, 8192 / 128), 512, SMEM_SZ>>>(
        th, tl, uh, ul, 256, 4096, bias, out);
}

// round 6
// speedup vs baseline: 4.6351x; 1.1211x over previous
#include <cuda_runtime.h>
#include <cuda_bf16.h>
#include <cstdint>

#define DEV_INLINE __device__ __forceinline__

// ---------------- scratch (device globals; allocation-free) ----------------
__device__ __align__(16) float g_vt[256u * 4096u];   // V rna-rounded to tf32
__device__ __align__(16) float g_ut[4096u * 256u];   // U rna-rounded to tf32
__device__ __align__(16) float g_t [8192u * 256u];   // T (pre-rounded to tf32)

// ---------------- PTX helpers ----------------
DEV_INLINE uint32_t smem_u32(const void* p) {
    uint32_t a;
    asm("{ .reg .u64 t; cvta.to.shared.u64 t, %1; cvt.u32.u64 %0, t; }"
        : "=r"(a) : "l"(p));
    return a;
}

DEV_INLINE float cvt_rna_tf32(float x) {
    float r;
    asm("cvt.rna.tf32.f32 %0, %1;" : "=f"(r) : "f"(x));
    return r;
}

#define CP_ASYNC16(dst, src) \
    asm volatile("cp.async.cg.shared.global [%0], [%1], 16;" :: "r"(dst), "l"(src))
#define CP_COMMIT() asm volatile("cp.async.commit_group;" ::: "memory")
#define CP_WAIT1()  asm volatile("cp.async.wait_group 1;" ::: "memory")

#define MMA_TF32(d, a, b) \
    asm volatile("mma.sync.aligned.m16n8k8.row.col.f32.tf32.tf32.f32 " \
                 "{%0,%1,%2,%3},{%4,%5,%6,%7},{%8,%9},{%0,%1,%2,%3};" \
                 : "+f"((d)[0]), "+f"((d)[1]), "+f"((d)[2]), "+f"((d)[3]) \
                 : "r"((a)[0]), "r"((a)[1]), "r"((a)[2]), "r"((a)[3]), \
                   "r"((b)[0]), "r"((b)[1]))

// ---------------- tiling constants ----------------
static constexpr int BM = 128, BN = 128, KT = 32;
static constexpr int NST = 3;
static constexpr int STRW = 36;                           // fp32 words per smem row (pad)
static constexpr uint32_t TILE_B  = 128u * STRW * 4u;     // 18432 B
static constexpr uint32_t STAGE_B = 2u * TILE_B;          // A, B
static constexpr uint32_t SMEM_SZ = NST * STAGE_B;        // 110592 B

// ---------------- rna-round V and U into scratch ----------------
__global__ void cvt_vu(const float* __restrict__ V, float* __restrict__ vt,
                       const float* __restrict__ U, float* __restrict__ ut, int n1) {
    int i = (blockIdx.x * 256 + threadIdx.x) * 4;
    const float* s; float* d;
    if (i < n1) { s = V; d = vt; }
    else        { s = U; d = ut; i -= n1; }
    float4 v = *reinterpret_cast<const float4*>(&s[i]);
    v.x = cvt_rna_tf32(v.x); v.y = cvt_rna_tf32(v.y);
    v.z = cvt_rna_tf32(v.z); v.w = cvt_rna_tf32(v.w);
    *reinterpret_cast<float4*>(&d[i]) = v;
}

// ---------------- shared TF32 MMA consumer ----------------
// warp tile 32x32, k32 = 4 x k8 steps; operands in padded row-major smem [128][STRW].
DEV_INLINE void consume_stage(const float* As, const float* Bs,
                              int wm, int wn, int lane, float acc[2][4][4]) {
    const int lr = lane >> 2;         // 0..7
    const int lc = lane & 3;          // 0..3
#pragma unroll
    for (int ks = 0; ks < 4; ks++) {
        const int c = ks * 8 + lc;
        uint32_t a[2][4], b[4][2];
#pragma unroll
        for (int mt = 0; mt < 2; mt++) {
            const int r = wm * 32 + mt * 16 + lr;
            a[mt][0] = __float_as_uint(As[r * STRW + c]);
            a[mt][1] = __float_as_uint(As[(r + 8) * STRW + c]);
            a[mt][2] = __float_as_uint(As[r * STRW + c + 4]);
            a[mt][3] = __float_as_uint(As[(r + 8) * STRW + c + 4]);
        }
#pragma unroll
        for (int nt = 0; nt < 4; nt++) {
            const int n = wn * 32 + nt * 8 + lr;
            b[nt][0] = __float_as_uint(Bs[n * STRW + c]);
            b[nt][1] = __float_as_uint(Bs[n * STRW + c + 4]);
        }
#pragma unroll
        for (int mt = 0; mt < 2; mt++)
#pragma unroll
            for (int nt = 0; nt < 4; nt++)
                MMA_TF32(acc[mt][nt], a[mt], b[nt]);
    }
}

// ---------------- Stage 1: T = x @ V^T (x fp32, rna in-kernel; V pre-rounded) ----------------
__global__ __launch_bounds__(512, 1)
void lr_gemm_s1(const float* __restrict__ X, const float* __restrict__ Bt,
                int K, int Nout, float* __restrict__ T) {
    extern __shared__ __align__(16) char smem[];
    float* sm = reinterpret_cast<float*>(smem);
    const uint32_t sb = smem_u32(smem);

    const int tid  = threadIdx.x;
    const int lane = tid & 31;
    const int warp = tid >> 5;
    const int wm = warp & 3, wn = warp >> 2;
    const int m0 = blockIdx.y * BM;
    const int n0 = blockIdx.x * BN;
    const int nk = K / KT;

    const float* Xb = X  + (size_t)m0 * K;
    const float* Bb = Bt + (size_t)n0 * K;

    // producer mapping: 128 rows x 32 floats = 1024 x 16B chunks; 512 thr x 2
    const int r0 = tid >> 3;              // 0..63
    const int kq = (tid & 7) * 4;         // 0,4,...,28
    const uint32_t pd0 = (uint32_t)(r0 * STRW + kq) * 4;
    const uint32_t pd1 = (uint32_t)((r0 + 64) * STRW + kq) * 4;

    auto produceB = [&](int j) {
        if (j < nk) {
            const uint32_t st = sb + (uint32_t)(j % NST) * STAGE_B + TILE_B;
            const size_t g0 = (size_t)r0 * K + j * KT + kq;
            CP_ASYNC16(st + pd0, Bb + g0);
            CP_ASYNC16(st + pd1, Bb + g0 + (size_t)64 * K);
        }
        CP_COMMIT();
    };

    float ra[8];
    auto loadA = [&](int j) {
        if (j < nk) {
            const size_t g0 = (size_t)r0 * K + j * KT + kq;
            float4 v0 = *reinterpret_cast<const float4*>(Xb + g0);
            float4 v1 = *reinterpret_cast<const float4*>(Xb + g0 + (size_t)64 * K);
            ra[0] = v0.x; ra[1] = v0.y; ra[2] = v0.z; ra[3] = v0.w;
            ra[4] = v1.x; ra[5] = v1.y; ra[6] = v1.z; ra[7] = v1.w;
        }
    };
    auto stsA = [&](int j) {
        const uint32_t off = (uint32_t)(j % NST) * STAGE_B;
        float4 v0, v1;
        v0.x = cvt_rna_tf32(ra[0]); v0.y = cvt_rna_tf32(ra[1]);
        v0.z = cvt_rna_tf32(ra[2]); v0.w = cvt_rna_tf32(ra[3]);
        v1.x = cvt_rna_tf32(ra[4]); v1.y = cvt_rna_tf32(ra[5]);
        v1.z = cvt_rna_tf32(ra[6]); v1.w = cvt_rna_tf32(ra[7]);
        *reinterpret_cast<float4*>(smem + off + pd0) = v0;
        *reinterpret_cast<float4*>(smem + off + pd1) = v1;
    };

    float acc[2][4][4];
#pragma unroll
    for (int mt = 0; mt < 2; mt++)
#pragma unroll
        for (int nt = 0; nt < 4; nt++)
#pragma unroll
            for (int e = 0; e < 4; e++) acc[mt][nt][e] = 0.0f;

    loadA(0);
    produceB(0);
    produceB(1);

    for (int i = 0; i < nk; i++) {
        stsA(i);
        loadA(i + 1);
        CP_WAIT1();
        __syncthreads();
        produceB(i + 2);
        const float* st = sm + (size_t)(i % NST) * (STAGE_B / 4);
        consume_stage(st, st + TILE_B / 4, wm, wn, lane, acc);
    }

    // epilogue: store T pre-rounded to tf32 (stage 2 consumes directly)
    const int er = lane >> 2, ec = (lane & 3) * 2;
#pragma unroll
    for (int nt = 0; nt < 4; nt++) {
        const int col = n0 + wn * 32 + nt * 8 + ec;
#pragma unroll
        for (int mt = 0; mt < 2; mt++) {
            const int r0g = m0 + wm * 32 + mt * 16 + er;
#pragma unroll
            for (int h = 0; h < 2; h++) {
                const int row = r0g + h * 8;
                float2 o = make_float2(cvt_rna_tf32(acc[mt][nt][h * 2 + 0]),
                                       cvt_rna_tf32(acc[mt][nt][h * 2 + 1]));
                *reinterpret_cast<float2*>(&T[(size_t)row * Nout + col]) = o;
            }
        }
    }
}

// ---------------- Stage 2: out = T @ U^T + bias (both operands pre-rounded) ----------------
__global__ __launch_bounds__(512, 1)
void lr_gemm_s2(const float* __restrict__ At, const float* __restrict__ Bt,
                int K, int Nout, const float* __restrict__ bias,
                float* __restrict__ Cf) {
    extern __shared__ __align__(16) char smem[];
    float* sm = reinterpret_cast<float*>(smem);
    const uint32_t sb = smem_u32(smem);

    const int tid  = threadIdx.x;
    const int lane = tid & 31;
    const int warp = tid >> 5;
    const int wm = warp & 3, wn = warp >> 2;
    const int m0 = blockIdx.y * BM;
    const int n0 = blockIdx.x * BN;
    const int nk = K / KT;

    const float* Ab = At + (size_t)m0 * K;
    const float* Bb = Bt + (size_t)n0 * K;

    const int r0 = tid >> 3;
    const int kq = (tid & 7) * 4;
    const uint32_t pd0 = (uint32_t)(r0 * STRW + kq) * 4;
    const uint32_t pd1 = (uint32_t)((r0 + 64) * STRW + kq) * 4;

    auto produce = [&](int j) {
        if (j < nk) {
            const uint32_t st = sb + (uint32_t)(j % NST) * STAGE_B;
            const size_t g0 = (size_t)r0 * K + j * KT + kq;
            CP_ASYNC16(st + pd0, Ab + g0);
            CP_ASYNC16(st + pd1, Ab + g0 + (size_t)64 * K);
            CP_ASYNC16(st + TILE_B + pd0, Bb + g0);
            CP_ASYNC16(st + TILE_B + pd1, Bb + g0 + (size_t)64 * K);
        }
        CP_COMMIT();
    };

    float acc[2][4][4];
#pragma unroll
    for (int mt = 0; mt < 2; mt++)
#pragma unroll
        for (int nt = 0; nt < 4; nt++)
#pragma unroll
            for (int e = 0; e < 4; e++) acc[mt][nt][e] = 0.0f;

    produce(0);
    produce(1);

    for (int i = 0; i < nk; i++) {
        CP_WAIT1();
        __syncthreads();
        produce(i + 2);
        const float* st = sm + (size_t)(i % NST) * (STAGE_B / 4);
        consume_stage(st, st + TILE_B / 4, wm, wn, lane, acc);
    }

    const int er = lane >> 2, ec = (lane & 3) * 2;
#pragma unroll
    for (int nt = 0; nt < 4; nt++) {
        const int col = n0 + wn * 32 + nt * 8 + ec;
        const float b0 = bias[col], b1 = bias[col + 1];
#pragma unroll
        for (int mt = 0; mt < 2; mt++) {
            const int r0g = m0 + wm * 32 + mt * 16 + er;
#pragma unroll
            for (int h = 0; h < 2; h++) {
                const int row = r0g + h * 8;
                float2 o = make_float2(acc[mt][nt][h * 2 + 0] + b0,
                                       acc[mt][nt][h * 2 + 1] + b1);
                *reinterpret_cast<float2*>(&Cf[(size_t)row * Nout + col]) = o;
            }
        }
    }
}

// ---------------- launch ----------------
extern "C" void kernel_launch(void* const* d_in, const int* in_sizes, int n_in,
                              void* d_out, int out_size) {
    const float* x    = (const float*)d_in[0];   // [8192, 4096]
    const float* U    = (const float*)d_in[1];   // [4096, 256]
    const float* V    = (const float*)d_in[2];   // [256, 4096]
    const float* bias = (const float*)d_in[3];   // [4096]
    float* out = (float*)d_out;                  // [8192, 4096]

    float *vt, *ut, *T;
    cudaGetSymbolAddress((void**)&vt, g_vt);
    cudaGetSymbolAddress((void**)&ut, g_ut);
    cudaGetSymbolAddress((void**)&T,  g_t);

    cudaFuncSetAttribute(lr_gemm_s1, cudaFuncAttributeMaxDynamicSharedMemorySize, SMEM_SZ);
    cudaFuncSetAttribute(lr_gemm_s2, cudaFuncAttributeMaxDynamicSharedMemorySize, SMEM_SZ);

    // rna-round V and U (one tiny launch)
    const int n1 = 256 * 4096;
    cvt_vu<<<(2 * n1 / 4) / 256, 256>>>(V, vt, U, ut, n1);

    // Stage 1: T[8192,256] = x @ V^T (K=4096)
    lr_gemm_s1<<<dim3(256 / 128, 8192 / 128), 512, SMEM_SZ>>>(x, vt, 4096, 256, T);

    // Stage 2: out[8192,4096] = T @ U^T + bias (K=256)
    lr_gemm_s2<<<dim3(4096 / 128, 8192 / 128), 512, SMEM_SZ>>>(T, ut, 256, 4096, bias, out);
}

// round 7
// speedup vs baseline: 4.6676x; 1.0070x over previous
#include <cuda_runtime.h>
#include <cuda_bf16.h>
#include <cstdint>

#define DEV_INLINE __device__ __forceinline__

// ---------------- scratch (device globals; allocation-free) ----------------
__device__ __align__(16) float g_vt[256u * 4096u];   // V rna-rounded to tf32
__device__ __align__(16) float g_ut[4096u * 256u];   // U rna-rounded to tf32
__device__ __align__(16) float g_t [8192u * 256u];   // T (pre-rounded to tf32)

// ---------------- PTX helpers ----------------
DEV_INLINE uint32_t smem_u32(const void* p) {
    uint32_t a;
    asm("{ .reg .u64 t; cvta.to.shared.u64 t, %1; cvt.u32.u64 %0, t; }"
        : "=r"(a) : "l"(p));
    return a;
}

DEV_INLINE float cvt_rna_tf32(float x) {
    float r;
    asm("cvt.rna.tf32.f32 %0, %1;" : "=f"(r) : "f"(x));
    return r;
}

#define CP_ASYNC16(dst, src) \
    asm volatile("cp.async.cg.shared.global [%0], [%1], 16;" :: "r"(dst), "l"(src))
#define CP_COMMIT() asm volatile("cp.async.commit_group;" ::: "memory")
#define CP_WAIT1()  asm volatile("cp.async.wait_group 1;" ::: "memory")

#define MMA_TF32(d, a, b) \
    asm volatile("mma.sync.aligned.m16n8k8.row.col.f32.tf32.tf32.f32 " \
                 "{%0,%1,%2,%3},{%4,%5,%6,%7},{%8,%9},{%0,%1,%2,%3};" \
                 : "+f"((d)[0]), "+f"((d)[1]), "+f"((d)[2]), "+f"((d)[3]) \
                 : "r"((a)[0]), "r"((a)[1]), "r"((a)[2]), "r"((a)[3]), \
                   "r"((b)[0]), "r"((b)[1]))

// ---------------- tiling constants ----------------
static constexpr int BM = 64, BN = 128, KT = 32;
static constexpr int NST = 3;
static constexpr int STRW = 36;                         // fp32 words per smem row (pad)
static constexpr uint32_t A_TILE_B = 64u  * STRW * 4u;  // 9216 B
static constexpr uint32_t B_TILE_B = 128u * STRW * 4u;  // 18432 B
static constexpr uint32_t STAGE_B  = A_TILE_B + B_TILE_B;  // 27648 B
static constexpr uint32_t SMEM_SZ  = NST * STAGE_B;        // 82944 B (occ 2)

// ---------------- rna-round V and U into scratch ----------------
__global__ void cvt_vu(const float* __restrict__ V, float* __restrict__ vt,
                       const float* __restrict__ U, float* __restrict__ ut, int n1) {
    int i = (blockIdx.x * 256 + threadIdx.x) * 4;
    const float* s; float* d;
    if (i < n1) { s = V; d = vt; }
    else        { s = U; d = ut; i -= n1; }
    float4 v = *reinterpret_cast<const float4*>(&s[i]);
    v.x = cvt_rna_tf32(v.x); v.y = cvt_rna_tf32(v.y);
    v.z = cvt_rna_tf32(v.z); v.w = cvt_rna_tf32(v.w);
    *reinterpret_cast<float4*>(&d[i]) = v;
}

// ---------------- shared TF32 MMA consumer ----------------
// warp tile 32x32 at (wm of 2, wn of 4); smem padded row-major A[64][STRW], B[128][STRW].
DEV_INLINE void consume_stage(const float* As, const float* Bs,
                              int wm, int wn, int lane, float acc[2][4][4]) {
    const int lr = lane >> 2;         // 0..7
    const int lc = lane & 3;          // 0..3
#pragma unroll
    for (int ks = 0; ks < 4; ks++) {
        const int c = ks * 8 + lc;
        uint32_t a[2][4], b[4][2];
#pragma unroll
        for (int mt = 0; mt < 2; mt++) {
            const int r = wm * 32 + mt * 16 + lr;
            a[mt][0] = __float_as_uint(As[r * STRW + c]);
            a[mt][1] = __float_as_uint(As[(r + 8) * STRW + c]);
            a[mt][2] = __float_as_uint(As[r * STRW + c + 4]);
            a[mt][3] = __float_as_uint(As[(r + 8) * STRW + c + 4]);
        }
#pragma unroll
        for (int nt = 0; nt < 4; nt++) {
            const int n = wn * 32 + nt * 8 + lr;
            b[nt][0] = __float_as_uint(Bs[n * STRW + c]);
            b[nt][1] = __float_as_uint(Bs[n * STRW + c + 4]);
        }
#pragma unroll
        for (int mt = 0; mt < 2; mt++)
#pragma unroll
            for (int nt = 0; nt < 4; nt++)
                MMA_TF32(acc[mt][nt], a[mt], b[nt]);
    }
}

// ---------------- Stage 1: T = x @ V^T (x fp32, rna in-kernel; V pre-rounded) ----------------
__global__ __launch_bounds__(256, 2)
void lr_gemm_s1(const float* __restrict__ X, const float* __restrict__ Bt,
                int K, int Nout, float* __restrict__ T) {
    extern __shared__ __align__(16) char smem[];
    float* sm = reinterpret_cast<float*>(smem);
    const uint32_t sb = smem_u32(smem);

    const int tid  = threadIdx.x;
    const int lane = tid & 31;
    const int warp = tid >> 5;
    const int wm = warp & 1, wn = warp >> 1;
    const int m0 = blockIdx.y * BM;
    const int n0 = blockIdx.x * BN;
    const int nk = K / KT;

    const float* Xb = X  + (size_t)m0 * K;
    const float* Bb = Bt + (size_t)n0 * K;

    // producer mapping: rows via tid>>3, cols via (tid&7)*4
    const int pr = tid >> 3;              // 0..31
    const int kq = (tid & 7) * 4;         // 0,4,...,28
    const uint32_t pa0 = (uint32_t)(pr * STRW + kq) * 4;
    const uint32_t pa1 = (uint32_t)((pr + 32) * STRW + kq) * 4;

    auto produceB = [&](int j) {
        if (j < nk) {
            const uint32_t st = sb + (uint32_t)(j % NST) * STAGE_B + A_TILE_B;
            const size_t g0 = (size_t)pr * K + j * KT + kq;
#pragma unroll
            for (int h = 0; h < 4; h++)
                CP_ASYNC16(st + pa0 + (uint32_t)h * 32u * STRW * 4u,
                           Bb + g0 + (size_t)(h * 32) * K);
        }
        CP_COMMIT();
    };

    float ra[8];
    auto loadA = [&](int j) {
        if (j < nk) {
            const size_t g0 = (size_t)pr * K + j * KT + kq;
            float4 v0 = *reinterpret_cast<const float4*>(Xb + g0);
            float4 v1 = *reinterpret_cast<const float4*>(Xb + g0 + (size_t)32 * K);
            ra[0] = v0.x; ra[1] = v0.y; ra[2] = v0.z; ra[3] = v0.w;
            ra[4] = v1.x; ra[5] = v1.y; ra[6] = v1.z; ra[7] = v1.w;
        }
    };
    auto stsA = [&](int j) {
        const uint32_t off = (uint32_t)(j % NST) * STAGE_B;
        float4 v0, v1;
        v0.x = cvt_rna_tf32(ra[0]); v0.y = cvt_rna_tf32(ra[1]);
        v0.z = cvt_rna_tf32(ra[2]); v0.w = cvt_rna_tf32(ra[3]);
        v1.x = cvt_rna_tf32(ra[4]); v1.y = cvt_rna_tf32(ra[5]);
        v1.z = cvt_rna_tf32(ra[6]); v1.w = cvt_rna_tf32(ra[7]);
        *reinterpret_cast<float4*>(smem + off + pa0) = v0;
        *reinterpret_cast<float4*>(smem + off + pa1) = v1;
    };

    float acc[2][4][4];
#pragma unroll
    for (int mt = 0; mt < 2; mt++)
#pragma unroll
        for (int nt = 0; nt < 4; nt++)
#pragma unroll
            for (int e = 0; e < 4; e++) acc[mt][nt][e] = 0.0f;

    loadA(0);
    produceB(0);
    produceB(1);

    for (int i = 0; i < nk; i++) {
        stsA(i);
        loadA(i + 1);
        CP_WAIT1();
        __syncthreads();
        produceB(i + 2);
        const float* st = sm + (size_t)(i % NST) * (STAGE_B / 4);
        consume_stage(st, st + A_TILE_B / 4, wm, wn, lane, acc);
    }

    // epilogue: store T pre-rounded to tf32
    const int er = lane >> 2, ec = (lane & 3) * 2;
#pragma unroll
    for (int nt = 0; nt < 4; nt++) {
        const int col = n0 + wn * 32 + nt * 8 + ec;
#pragma unroll
        for (int mt = 0; mt < 2; mt++) {
            const int r0g = m0 + wm * 32 + mt * 16 + er;
#pragma unroll
            for (int h = 0; h < 2; h++) {
                const int row = r0g + h * 8;
                float2 o = make_float2(cvt_rna_tf32(acc[mt][nt][h * 2 + 0]),
                                       cvt_rna_tf32(acc[mt][nt][h * 2 + 1]));
                *reinterpret_cast<float2*>(&T[(size_t)row * Nout + col]) = o;
            }
        }
    }
}

// ---------------- Stage 2: out = T @ U^T + bias (both operands pre-rounded) ----------------
__global__ __launch_bounds__(256, 2)
void lr_gemm_s2(const float* __restrict__ At, const float* __restrict__ Bt,
                int K, int Nout, const float* __restrict__ bias,
                float* __restrict__ Cf) {
    extern __shared__ __align__(16) char smem[];
    float* sm = reinterpret_cast<float*>(smem);
    const uint32_t sb = smem_u32(smem);

    const int tid  = threadIdx.x;
    const int lane = tid & 31;
    const int warp = tid >> 5;
    const int wm = warp & 1, wn = warp >> 1;
    const int m0 = blockIdx.y * BM;
    const int n0 = blockIdx.x * BN;
    const int nk = K / KT;

    const float* Ab = At + (size_t)m0 * K;
    const float* Bb = Bt + (size_t)n0 * K;

    const int pr = tid >> 3;
    const int kq = (tid & 7) * 4;
    const uint32_t pa0 = (uint32_t)(pr * STRW + kq) * 4;

    auto produce = [&](int j) {
        if (j < nk) {
            const uint32_t st = sb + (uint32_t)(j % NST) * STAGE_B;
            const size_t g0 = (size_t)pr * K + j * KT + kq;
            // A tile: 64 rows
#pragma unroll
            for (int h = 0; h < 2; h++)
                CP_ASYNC16(st + pa0 + (uint32_t)h * 32u * STRW * 4u,
                           Ab + g0 + (size_t)(h * 32) * K);
            // B tile: 128 rows
#pragma unroll
            for (int h = 0; h < 4; h++)
                CP_ASYNC16(st + A_TILE_B + pa0 + (uint32_t)h * 32u * STRW * 4u,
                           Bb + g0 + (size_t)(h * 32) * K);
        }
        CP_COMMIT();
    };

    float acc[2][4][4];
#pragma unroll
    for (int mt = 0; mt < 2; mt++)
#pragma unroll
        for (int nt = 0; nt < 4; nt++)
#pragma unroll
            for (int e = 0; e < 4; e++) acc[mt][nt][e] = 0.0f;

    produce(0);
    produce(1);

    for (int i = 0; i < nk; i++) {
        CP_WAIT1();
        __syncthreads();
        produce(i + 2);
        const float* st = sm + (size_t)(i % NST) * (STAGE_B / 4);
        consume_stage(st, st + A_TILE_B / 4, wm, wn, lane, acc);
    }

    const int er = lane >> 2, ec = (lane & 3) * 2;
#pragma unroll
    for (int nt = 0; nt < 4; nt++) {
        const int col = n0 + wn * 32 + nt * 8 + ec;
        const float b0 = bias[col], b1 = bias[col + 1];
#pragma unroll
        for (int mt = 0; mt < 2; mt++) {
            const int r0g = m0 + wm * 32 + mt * 16 + er;
#pragma unroll
            for (int h = 0; h < 2; h++) {
                const int row = r0g + h * 8;
                float2 o = make_float2(acc[mt][nt][h * 2 + 0] + b0,
                                       acc[mt][nt][h * 2 + 1] + b1);
                *reinterpret_cast<float2*>(&Cf[(size_t)row * Nout + col]) = o;
            }
        }
    }
}

// ---------------- launch ----------------
extern "C" void kernel_launch(void* const* d_in, const int* in_sizes, int n_in,
                              void* d_out, int out_size) {
    const float* x    = (const float*)d_in[0];   // [8192, 4096]
    const float* U    = (const float*)d_in[1];   // [4096, 256]
    const float* V    = (const float*)d_in[2];   // [256, 4096]
    const float* bias = (const float*)d_in[3];   // [4096]
    float* out = (float*)d_out;                  // [8192, 4096]

    float *vt, *ut, *T;
    cudaGetSymbolAddress((void**)&vt, g_vt);
    cudaGetSymbolAddress((void**)&ut, g_ut);
    cudaGetSymbolAddress((void**)&T,  g_t);

    cudaFuncSetAttribute(lr_gemm_s1, cudaFuncAttributeMaxDynamicSharedMemorySize, SMEM_SZ);
    cudaFuncSetAttribute(lr_gemm_s2, cudaFuncAttributeMaxDynamicSharedMemorySize, SMEM_SZ);

    // rna-round V and U (one tiny launch)
    const int n1 = 256 * 4096;
    cvt_vu<<<(2 * n1 / 4) / 256, 256>>>(V, vt, U, ut, n1);

    // Stage 1: T[8192,256] = x @ V^T (K=4096): 256 CTAs, occ 2
    lr_gemm_s1<<<dim3(256 / BN, 8192 / BM), 256, SMEM_SZ>>>(x, vt, 4096, 256, T);

    // Stage 2: out[8192,4096] = T @ U^T + bias (K=256): 4096 CTAs, occ 2
    lr_gemm_s2<<<dim3(4096 / BN, 8192 / BM), 256, SMEM_SZ>>>(T, ut, 256, 4096, bias, out);
}

// round 8
// speedup vs baseline: 4.9881x; 1.0687x over previous
#include <cuda_runtime.h>
#include <cuda_bf16.h>
#include <cstdint>

#define DEV_INLINE __device__ __forceinline__

// ---------------- scratch (device globals; allocation-free) ----------------
__device__ __align__(16) float g_vt[256u * 4096u];   // V rna-rounded to tf32
__device__ __align__(16) float g_ut[4096u * 256u];   // U rna-rounded to tf32
__device__ __align__(16) float g_t [8192u * 256u];   // T (pre-rounded to tf32)

// ---------------- PTX helpers ----------------
DEV_INLINE uint32_t smem_u32(const void* p) {
    uint32_t a;
    asm("{ .reg .u64 t; cvta.to.shared.u64 t, %1; cvt.u32.u64 %0, t; }"
        : "=r"(a) : "l"(p));
    return a;
}

DEV_INLINE float cvt_rna_tf32(float x) {
    float r;
    asm("cvt.rna.tf32.f32 %0, %1;" : "=f"(r) : "f"(x));
    return r;
}

#define CP_ASYNC16(dst, src) \
    asm volatile("cp.async.cg.shared.global [%0], [%1], 16;" :: "r"(dst), "l"(src))
#define CP_COMMIT() asm volatile("cp.async.commit_group;" ::: "memory")
#define CP_WAIT1()  asm volatile("cp.async.wait_group 1;" ::: "memory")

#define MMA_TF32(d, a, b) \
    asm volatile("mma.sync.aligned.m16n8k8.row.col.f32.tf32.tf32.f32 " \
                 "{%0,%1,%2,%3},{%4,%5,%6,%7},{%8,%9},{%0,%1,%2,%3};" \
                 : "+f"((d)[0]), "+f"((d)[1]), "+f"((d)[2]), "+f"((d)[3]) \
                 : "r"((a)[0]), "r"((a)[1]), "r"((a)[2]), "r"((a)[3]), \
                   "r"((b)[0]), "r"((b)[1]))

// ---------------- tiling constants ----------------
static constexpr int KT = 32;
static constexpr int NST = 3;
static constexpr int STRW = 36;                          // fp32 words per smem row (pad)
// stage 1: BM=64, BN=128
static constexpr uint32_t A1_TILE_B = 64u  * STRW * 4u;  // 9216 B
static constexpr uint32_t B1_TILE_B = 128u * STRW * 4u;  // 18432 B
static constexpr uint32_t STAGE1_B  = A1_TILE_B + B1_TILE_B;
static constexpr uint32_t SMEM1_SZ  = NST * STAGE1_B;    // 82944 B (occ 2)
// stage 2: BM=128, BN=128
static constexpr uint32_t A2_TILE_B = 128u * STRW * 4u;  // 18432 B
static constexpr uint32_t STAGE2_B  = 2u * A2_TILE_B;    // 36864 B
static constexpr uint32_t SMEM2_SZ  = NST * STAGE2_B;    // 110592 B (occ 2: 216KB/SM)

// ---------------- rna-round V and U into scratch ----------------
__global__ void cvt_vu(const float* __restrict__ V, float* __restrict__ vt,
                       const float* __restrict__ U, float* __restrict__ ut, int n1) {
    int i = (blockIdx.x * 256 + threadIdx.x) * 4;
    const float* s; float* d;
    if (i < n1) { s = V; d = vt; }
    else        { s = U; d = ut; i -= n1; }
    float4 v = *reinterpret_cast<const float4*>(&s[i]);
    v.x = cvt_rna_tf32(v.x); v.y = cvt_rna_tf32(v.y);
    v.z = cvt_rna_tf32(v.z); v.w = cvt_rna_tf32(v.w);
    *reinterpret_cast<float4*>(&d[i]) = v;
}

// ---------------- Stage 1: T = x @ V^T (x fp32, rna in-kernel; V pre-rounded) ----------------
// BM=64, BN=128, 256 thr, warp tile 32x32 (2 wm x 4 wn). Unchanged from R7.
__global__ __launch_bounds__(256, 2)
void lr_gemm_s1(const float* __restrict__ X, const float* __restrict__ Bt,
                int K, int Nout, float* __restrict__ T) {
    extern __shared__ __align__(16) char smem[];
    float* sm = reinterpret_cast<float*>(smem);
    const uint32_t sb = smem_u32(smem);

    const int tid  = threadIdx.x;
    const int lane = tid & 31;
    const int warp = tid >> 5;
    const int wm = warp & 1, wn = warp >> 1;
    const int m0 = blockIdx.y * 64;
    const int n0 = blockIdx.x * 128;
    const int nk = K / KT;

    const float* Xb = X  + (size_t)m0 * K;
    const float* Bb = Bt + (size_t)n0 * K;

    const int pr = tid >> 3;              // 0..31
    const int kq = (tid & 7) * 4;         // 0,4,...,28
    const uint32_t pa0 = (uint32_t)(pr * STRW + kq) * 4;
    const uint32_t pa1 = (uint32_t)((pr + 32) * STRW + kq) * 4;

    auto produceB = [&](int j) {
        if (j < nk) {
            const uint32_t st = sb + (uint32_t)(j % NST) * STAGE1_B + A1_TILE_B;
            const size_t g0 = (size_t)pr * K + j * KT + kq;
#pragma unroll
            for (int h = 0; h < 4; h++)
                CP_ASYNC16(st + pa0 + (uint32_t)h * 32u * STRW * 4u,
                           Bb + g0 + (size_t)(h * 32) * K);
        }
        CP_COMMIT();
    };

    float ra[8];
    auto loadA = [&](int j) {
        if (j < nk) {
            const size_t g0 = (size_t)pr * K + j * KT + kq;
            float4 v0 = *reinterpret_cast<const float4*>(Xb + g0);
            float4 v1 = *reinterpret_cast<const float4*>(Xb + g0 + (size_t)32 * K);
            ra[0] = v0.x; ra[1] = v0.y; ra[2] = v0.z; ra[3] = v0.w;
            ra[4] = v1.x; ra[5] = v1.y; ra[6] = v1.z; ra[7] = v1.w;
        }
    };
    auto stsA = [&](int j) {
        const uint32_t off = (uint32_t)(j % NST) * STAGE1_B;
        float4 v0, v1;
        v0.x = cvt_rna_tf32(ra[0]); v0.y = cvt_rna_tf32(ra[1]);
        v0.z = cvt_rna_tf32(ra[2]); v0.w = cvt_rna_tf32(ra[3]);
        v1.x = cvt_rna_tf32(ra[4]); v1.y = cvt_rna_tf32(ra[5]);
        v1.z = cvt_rna_tf32(ra[6]); v1.w = cvt_rna_tf32(ra[7]);
        *reinterpret_cast<float4*>(smem + off + pa0) = v0;
        *reinterpret_cast<float4*>(smem + off + pa1) = v1;
    };

    float acc[2][4][4];
#pragma unroll
    for (int mt = 0; mt < 2; mt++)
#pragma unroll
        for (int nt = 0; nt < 4; nt++)
#pragma unroll
            for (int e = 0; e < 4; e++) acc[mt][nt][e] = 0.0f;

    const int lr = lane >> 2, lc = lane & 3;

    loadA(0);
    produceB(0);
    produceB(1);

    for (int i = 0; i < nk; i++) {
        stsA(i);
        loadA(i + 1);
        CP_WAIT1();
        __syncthreads();
        produceB(i + 2);
        const float* As = sm + (size_t)(i % NST) * (STAGE1_B / 4);
        const float* Bs = As + A1_TILE_B / 4;
#pragma unroll
        for (int ks = 0; ks < 4; ks++) {
            const int c = ks * 8 + lc;
            uint32_t a[2][4], b[4][2];
#pragma unroll
            for (int mt = 0; mt < 2; mt++) {
                const int r = wm * 32 + mt * 16 + lr;
                a[mt][0] = __float_as_uint(As[r * STRW + c]);
                a[mt][1] = __float_as_uint(As[(r + 8) * STRW + c]);
                a[mt][2] = __float_as_uint(As[r * STRW + c + 4]);
                a[mt][3] = __float_as_uint(As[(r + 8) * STRW + c + 4]);
            }
#pragma unroll
            for (int nt = 0; nt < 4; nt++) {
                const int n = wn * 32 + nt * 8 + lr;
                b[nt][0] = __float_as_uint(Bs[n * STRW + c]);
                b[nt][1] = __float_as_uint(Bs[n * STRW + c + 4]);
            }
#pragma unroll
            for (int mt = 0; mt < 2; mt++)
#pragma unroll
                for (int nt = 0; nt < 4; nt++)
                    MMA_TF32(acc[mt][nt], a[mt], b[nt]);
        }
    }

    // epilogue: store T pre-rounded to tf32
    const int er = lane >> 2, ec = (lane & 3) * 2;
#pragma unroll
    for (int nt = 0; nt < 4; nt++) {
        const int col = n0 + wn * 32 + nt * 8 + ec;
#pragma unroll
        for (int mt = 0; mt < 2; mt++) {
            const int r0g = m0 + wm * 32 + mt * 16 + er;
#pragma unroll
            for (int h = 0; h < 2; h++) {
                const int row = r0g + h * 8;
                float2 o = make_float2(cvt_rna_tf32(acc[mt][nt][h * 2 + 0]),
                                       cvt_rna_tf32(acc[mt][nt][h * 2 + 1]));
                *reinterpret_cast<float2*>(&T[(size_t)row * Nout + col]) = o;
            }
        }
    }
}

// ---------------- Stage 2: out = T @ U^T + bias ----------------
// BM=128, BN=128, 256 thr, warp tile 64x32 (2 wm x 4 wn, mt=4). Occ 2.
__global__ __launch_bounds__(256, 2)
void lr_gemm_s2(const float* __restrict__ At, const float* __restrict__ Bt,
                int K, int Nout, const float* __restrict__ bias,
                float* __restrict__ Cf) {
    extern __shared__ __align__(16) char smem[];
    float* sm = reinterpret_cast<float*>(smem);
    const uint32_t sb = smem_u32(smem);

    const int tid  = threadIdx.x;
    const int lane = tid & 31;
    const int warp = tid >> 5;
    const int wm = warp & 1, wn = warp >> 1;
    const int m0 = blockIdx.y * 128;
    const int n0 = blockIdx.x * 128;
    const int nk = K / KT;

    const float* Ab = At + (size_t)m0 * K;
    const float* Bb = Bt + (size_t)n0 * K;

    const int pr = tid >> 3;              // 0..31
    const int kq = (tid & 7) * 4;
    const uint32_t pa0 = (uint32_t)(pr * STRW + kq) * 4;

    auto produce = [&](int j) {
        if (j < nk) {
            const uint32_t st = sb + (uint32_t)(j % NST) * STAGE2_B;
            const size_t g0 = (size_t)pr * K + j * KT + kq;
#pragma unroll
            for (int h = 0; h < 4; h++)
                CP_ASYNC16(st + pa0 + (uint32_t)h * 32u * STRW * 4u,
                           Ab + g0 + (size_t)(h * 32) * K);
#pragma unroll
            for (int h = 0; h < 4; h++)
                CP_ASYNC16(st + A2_TILE_B + pa0 + (uint32_t)h * 32u * STRW * 4u,
                           Bb + g0 + (size_t)(h * 32) * K);
        }
        CP_COMMIT();
    };

    float acc[4][4][4];
#pragma unroll
    for (int mt = 0; mt < 4; mt++)
#pragma unroll
        for (int nt = 0; nt < 4; nt++)
#pragma unroll
            for (int e = 0; e < 4; e++) acc[mt][nt][e] = 0.0f;

    const int lr = lane >> 2, lc = lane & 3;

    produce(0);
    produce(1);

    for (int i = 0; i < nk; i++) {
        CP_WAIT1();
        __syncthreads();
        produce(i + 2);
        const float* As = sm + (size_t)(i % NST) * (STAGE2_B / 4);
        const float* Bs = As + A2_TILE_B / 4;
#pragma unroll
        for (int ks = 0; ks < 4; ks++) {
            const int c = ks * 8 + lc;
            uint32_t a[4][4], b[4][2];
#pragma unroll
            for (int mt = 0; mt < 4; mt++) {
                const int r = wm * 64 + mt * 16 + lr;
                a[mt][0] = __float_as_uint(As[r * STRW + c]);
                a[mt][1] = __float_as_uint(As[(r + 8) * STRW + c]);
                a[mt][2] = __float_as_uint(As[r * STRW + c + 4]);
                a[mt][3] = __float_as_uint(As[(r + 8) * STRW + c + 4]);
            }
#pragma unroll
            for (int nt = 0; nt < 4; nt++) {
                const int n = wn * 32 + nt * 8 + lr;
                b[nt][0] = __float_as_uint(Bs[n * STRW + c]);
                b[nt][1] = __float_as_uint(Bs[n * STRW + c + 4]);
            }
#pragma unroll
            for (int mt = 0; mt < 4; mt++)
#pragma unroll
                for (int nt = 0; nt < 4; nt++)
                    MMA_TF32(acc[mt][nt], a[mt], b[nt]);
        }
    }

    const int er = lane >> 2, ec = (lane & 3) * 2;
#pragma unroll
    for (int nt = 0; nt < 4; nt++) {
        const int col = n0 + wn * 32 + nt * 8 + ec;
        const float b0 = bias[col], b1 = bias[col + 1];
#pragma unroll
        for (int mt = 0; mt < 4; mt++) {
            const int r0g = m0 + wm * 64 + mt * 16 + er;
#pragma unroll
            for (int h = 0; h < 2; h++) {
                const int row = r0g + h * 8;
                float2 o = make_float2(acc[mt][nt][h * 2 + 0] + b0,
                                       acc[mt][nt][h * 2 + 1] + b1);
                *reinterpret_cast<float2*>(&Cf[(size_t)row * Nout + col]) = o;
            }
        }
    }
}

// ---------------- launch ----------------
extern "C" void kernel_launch(void* const* d_in, const int* in_sizes, int n_in,
                              void* d_out, int out_size) {
    const float* x    = (const float*)d_in[0];   // [8192, 4096]
    const float* U    = (const float*)d_in[1];   // [4096, 256]
    const float* V    = (const float*)d_in[2];   // [256, 4096]
    const float* bias = (const float*)d_in[3];   // [4096]
    float* out = (float*)d_out;                  // [8192, 4096]

    float *vt, *ut, *T;
    cudaGetSymbolAddress((void**)&vt, g_vt);
    cudaGetSymbolAddress((void**)&ut, g_ut);
    cudaGetSymbolAddress((void**)&T,  g_t);

    cudaFuncSetAttribute(lr_gemm_s1, cudaFuncAttributeMaxDynamicSharedMemorySize, SMEM1_SZ);
    cudaFuncSetAttribute(lr_gemm_s2, cudaFuncAttributeMaxDynamicSharedMemorySize, SMEM2_SZ);

    // rna-round V and U (one tiny launch)
    const int n1 = 256 * 4096;
    cvt_vu<<<(2 * n1 / 4) / 256, 256>>>(V, vt, U, ut, n1);

    // Stage 1: T[8192,256] = x @ V^T (K=4096): 256 CTAs, occ 2
    lr_gemm_s1<<<dim3(256 / 128, 8192 / 64), 256, SMEM1_SZ>>>(x, vt, 4096, 256, T);

    // Stage 2: out[8192,4096] = T @ U^T + bias (K=256): 2048 CTAs, BM=128, occ 2
    lr_gemm_s2<<<dim3(4096 / 128, 8192 / 128), 256, SMEM2_SZ>>>(T, ut, 256, 4096, bias, out);
}

// round 9
// speedup vs baseline: 5.1984x; 1.0421x over previous
#include <cuda_runtime.h>
#include <cuda_bf16.h>
#include <cstdint>

#define DEV_INLINE __device__ __forceinline__

// ---------------- scratch (device globals; allocation-free) ----------------
__device__ __align__(16) float g_vt[256u * 4096u];   // V rna-rounded to tf32
__device__ __align__(16) float g_ut[4096u * 256u];   // U rna-rounded to tf32
__device__ __align__(16) float g_t [8192u * 256u];   // T (pre-rounded to tf32)

// ---------------- PTX helpers ----------------
DEV_INLINE uint32_t smem_u32(const void* p) {
    uint32_t a;
    asm("{ .reg .u64 t; cvta.to.shared.u64 t, %1; cvt.u32.u64 %0, t; }"
        : "=r"(a) : "l"(p));
    return a;
}

DEV_INLINE float cvt_rna_tf32(float x) {
    float r;
    asm("cvt.rna.tf32.f32 %0, %1;" : "=f"(r) : "f"(x));
    return r;
}

#define CP_ASYNC16(dst, src) \
    asm volatile("cp.async.cg.shared.global [%0], [%1], 16;" :: "r"(dst), "l"(src))
#define CP_COMMIT() asm volatile("cp.async.commit_group;" ::: "memory")
#define CP_WAIT1()  asm volatile("cp.async.wait_group 1;" ::: "memory")
#define CP_WAIT2()  asm volatile("cp.async.wait_group 2;" ::: "memory")

#define MMA_TF32(d, a, b) \
    asm volatile("mma.sync.aligned.m16n8k8.row.col.f32.tf32.tf32.f32 " \
                 "{%0,%1,%2,%3},{%4,%5,%6,%7},{%8,%9},{%0,%1,%2,%3};" \
                 : "+f"((d)[0]), "+f"((d)[1]), "+f"((d)[2]), "+f"((d)[3]) \
                 : "r"((a)[0]), "r"((a)[1]), "r"((a)[2]), "r"((a)[3]), \
                   "r"((b)[0]), "r"((b)[1]))

// ---------------- tiling constants ----------------
static constexpr int KT = 32;
static constexpr int STRW = 36;                          // fp32 words per smem row (pad)
// stage 1: BM=64, BN=128, NST=4
static constexpr int NST1 = 4;
static constexpr uint32_t A1_TILE_B = 64u  * STRW * 4u;  // 9216 B
static constexpr uint32_t B1_TILE_B = 128u * STRW * 4u;  // 18432 B
static constexpr uint32_t STAGE1_B  = A1_TILE_B + B1_TILE_B;  // 27648 B
static constexpr uint32_t SMEM1_SZ  = NST1 * STAGE1_B;        // 110592 B (occ 2)
// stage 2: BM=128, BN=128, NST=3
static constexpr int NST2 = 3;
static constexpr uint32_t A2_TILE_B = 128u * STRW * 4u;  // 18432 B
static constexpr uint32_t STAGE2_B  = 2u * A2_TILE_B;    // 36864 B
static constexpr uint32_t SMEM2_SZ  = NST2 * STAGE2_B;   // 110592 B (occ 2)

// ---------------- rna-round V and U into scratch ----------------
__global__ void cvt_vu(const float* __restrict__ V, float* __restrict__ vt,
                       const float* __restrict__ U, float* __restrict__ ut, int n1) {
    int i = (blockIdx.x * 256 + threadIdx.x) * 4;
    const float* s; float* d;
    if (i < n1) { s = V; d = vt; }
    else        { s = U; d = ut; i -= n1; }
    float4 v = *reinterpret_cast<const float4*>(&s[i]);
    v.x = cvt_rna_tf32(v.x); v.y = cvt_rna_tf32(v.y);
    v.z = cvt_rna_tf32(v.z); v.w = cvt_rna_tf32(v.w);
    *reinterpret_cast<float4*>(&d[i]) = v;
}

// ---------------- Stage 1: T = x @ V^T ----------------
// x fed as raw fp32 (tf32 MMA truncates mantissa in HW); V pre-rounded rna.
// BM=64, BN=128, 256 thr, warp tile 32x32 (2 wm x 4 wn), NST=4, occ 2.
__global__ __launch_bounds__(256, 2)
void lr_gemm_s1(const float* __restrict__ X, const float* __restrict__ Bt,
                int K, int Nout, float* __restrict__ T) {
    extern __shared__ __align__(16) char smem[];
    float* sm = reinterpret_cast<float*>(smem);
    const uint32_t sb = smem_u32(smem);

    const int tid  = threadIdx.x;
    const int lane = tid & 31;
    const int warp = tid >> 5;
    const int wm = warp & 1, wn = warp >> 1;
    const int m0 = blockIdx.y * 64;
    const int n0 = blockIdx.x * 128;
    const int nk = K / KT;

    const float* Xb = X  + (size_t)m0 * K;
    const float* Bb = Bt + (size_t)n0 * K;

    const int pr = tid >> 3;              // 0..31
    const int kq = (tid & 7) * 4;         // 0,4,...,28
    const uint32_t pa0 = (uint32_t)(pr * STRW + kq) * 4;

    auto produce = [&](int j) {
        if (j < nk) {
            const uint32_t st = sb + (uint32_t)(j % NST1) * STAGE1_B;
            const size_t g0 = (size_t)pr * K + j * KT + kq;
            // A tile (x, raw fp32): 64 rows
#pragma unroll
            for (int h = 0; h < 2; h++)
                CP_ASYNC16(st + pa0 + (uint32_t)h * 32u * STRW * 4u,
                           Xb + g0 + (size_t)(h * 32) * K);
            // B tile (V tf32): 128 rows
#pragma unroll
            for (int h = 0; h < 4; h++)
                CP_ASYNC16(st + A1_TILE_B + pa0 + (uint32_t)h * 32u * STRW * 4u,
                           Bb + g0 + (size_t)(h * 32) * K);
        }
        CP_COMMIT();
    };

    float acc[2][4][4];
#pragma unroll
    for (int mt = 0; mt < 2; mt++)
#pragma unroll
        for (int nt = 0; nt < 4; nt++)
#pragma unroll
            for (int e = 0; e < 4; e++) acc[mt][nt][e] = 0.0f;

    const int lr = lane >> 2, lc = lane & 3;

    produce(0);
    produce(1);
    produce(2);

    for (int i = 0; i < nk; i++) {
        CP_WAIT2();            // groups pending: i+1, i+2 -> group i done
        __syncthreads();       // all threads done consuming iter i-1
        produce(i + 3);        // overwrites stage (i-1)%4 — safe after sync
        const float* As = sm + (size_t)(i % NST1) * (STAGE1_B / 4);
        const float* Bs = As + A1_TILE_B / 4;
#pragma unroll
        for (int ks = 0; ks < 4; ks++) {
            const int c = ks * 8 + lc;
            uint32_t a[2][4], b[4][2];
#pragma unroll
            for (int mt = 0; mt < 2; mt++) {
                const int r = wm * 32 + mt * 16 + lr;
                a[mt][0] = __float_as_uint(As[r * STRW + c]);
                a[mt][1] = __float_as_uint(As[(r + 8) * STRW + c]);
                a[mt][2] = __float_as_uint(As[r * STRW + c + 4]);
                a[mt][3] = __float_as_uint(As[(r + 8) * STRW + c + 4]);
            }
#pragma unroll
            for (int nt = 0; nt < 4; nt++) {
                const int n = wn * 32 + nt * 8 + lr;
                b[nt][0] = __float_as_uint(Bs[n * STRW + c]);
                b[nt][1] = __float_as_uint(Bs[n * STRW + c + 4]);
            }
#pragma unroll
            for (int mt = 0; mt < 2; mt++)
#pragma unroll
                for (int nt = 0; nt < 4; nt++)
                    MMA_TF32(acc[mt][nt], a[mt], b[nt]);
        }
    }

    // epilogue: store T pre-rounded rna to tf32
    const int er = lane >> 2, ec = (lane & 3) * 2;
#pragma unroll
    for (int nt = 0; nt < 4; nt++) {
        const int col = n0 + wn * 32 + nt * 8 + ec;
#pragma unroll
        for (int mt = 0; mt < 2; mt++) {
            const int r0g = m0 + wm * 32 + mt * 16 + er;
#pragma unroll
            for (int h = 0; h < 2; h++) {
                const int row = r0g + h * 8;
                float2 o = make_float2(cvt_rna_tf32(acc[mt][nt][h * 2 + 0]),
                                       cvt_rna_tf32(acc[mt][nt][h * 2 + 1]));
                *reinterpret_cast<float2*>(&T[(size_t)row * Nout + col]) = o;
            }
        }
    }
}

// ---------------- Stage 2: out = T @ U^T + bias ----------------
// BM=128, BN=128, 256 thr, warp tile 64x32 (2 wm x 4 wn, mt=4). NST=3, occ 2.
__global__ __launch_bounds__(256, 2)
void lr_gemm_s2(const float* __restrict__ At, const float* __restrict__ Bt,
                int K, int Nout, const float* __restrict__ bias,
                float* __restrict__ Cf) {
    extern __shared__ __align__(16) char smem[];
    float* sm = reinterpret_cast<float*>(smem);
    const uint32_t sb = smem_u32(smem);

    const int tid  = threadIdx.x;
    const int lane = tid & 31;
    const int warp = tid >> 5;
    const int wm = warp & 1, wn = warp >> 1;
    const int m0 = blockIdx.y * 128;
    const int n0 = blockIdx.x * 128;
    const int nk = K / KT;

    const float* Ab = At + (size_t)m0 * K;
    const float* Bb = Bt + (size_t)n0 * K;

    const int pr = tid >> 3;              // 0..31
    const int kq = (tid & 7) * 4;
    const uint32_t pa0 = (uint32_t)(pr * STRW + kq) * 4;

    auto produce = [&](int j) {
        if (j < nk) {
            const uint32_t st = sb + (uint32_t)(j % NST2) * STAGE2_B;
            const size_t g0 = (size_t)pr * K + j * KT + kq;
#pragma unroll
            for (int h = 0; h < 4; h++)
                CP_ASYNC16(st + pa0 + (uint32_t)h * 32u * STRW * 4u,
                           Ab + g0 + (size_t)(h * 32) * K);
#pragma unroll
            for (int h = 0; h < 4; h++)
                CP_ASYNC16(st + A2_TILE_B + pa0 + (uint32_t)h * 32u * STRW * 4u,
                           Bb + g0 + (size_t)(h * 32) * K);
        }
        CP_COMMIT();
    };

    float acc[4][4][4];
#pragma unroll
    for (int mt = 0; mt < 4; mt++)
#pragma unroll
        for (int nt = 0; nt < 4; nt++)
#pragma unroll
            for (int e = 0; e < 4; e++) acc[mt][nt][e] = 0.0f;

    const int lr = lane >> 2, lc = lane & 3;

    produce(0);
    produce(1);

    for (int i = 0; i < nk; i++) {
        CP_WAIT1();
        __syncthreads();
        produce(i + 2);
        const float* As = sm + (size_t)(i % NST2) * (STAGE2_B / 4);
        const float* Bs = As + A2_TILE_B / 4;
#pragma unroll
        for (int ks = 0; ks < 4; ks++) {
            const int c = ks * 8 + lc;
            uint32_t a[4][4], b[4][2];
#pragma unroll
            for (int mt = 0; mt < 4; mt++) {
                const int r = wm * 64 + mt * 16 + lr;
                a[mt][0] = __float_as_uint(As[r * STRW + c]);
                a[mt][1] = __float_as_uint(As[(r + 8) * STRW + c]);
                a[mt][2] = __float_as_uint(As[r * STRW + c + 4]);
                a[mt][3] = __float_as_uint(As[(r + 8) * STRW + c + 4]);
            }
#pragma unroll
            for (int nt = 0; nt < 4; nt++) {
                const int n = wn * 32 + nt * 8 + lr;
                b[nt][0] = __float_as_uint(Bs[n * STRW + c]);
                b[nt][1] = __float_as_uint(Bs[n * STRW + c + 4]);
            }
#pragma unroll
            for (int mt = 0; mt < 4; mt++)
#pragma unroll
                for (int nt = 0; nt < 4; nt++)
                    MMA_TF32(acc[mt][nt], a[mt], b[nt]);
        }
    }

    const int er = lane >> 2, ec = (lane & 3) * 2;
#pragma unroll
    for (int nt = 0; nt < 4; nt++) {
        const int col = n0 + wn * 32 + nt * 8 + ec;
        const float b0 = bias[col], b1 = bias[col + 1];
#pragma unroll
        for (int mt = 0; mt < 4; mt++) {
            const int r0g = m0 + wm * 64 + mt * 16 + er;
#pragma unroll
            for (int h = 0; h < 2; h++) {
                const int row = r0g + h * 8;
                float2 o = make_float2(acc[mt][nt][h * 2 + 0] + b0,
                                       acc[mt][nt][h * 2 + 1] + b1);
                *reinterpret_cast<float2*>(&Cf[(size_t)row * Nout + col]) = o;
            }
        }
    }
}

// ---------------- launch ----------------
extern "C" void kernel_launch(void* const* d_in, const int* in_sizes, int n_in,
                              void* d_out, int out_size) {
    const float* x    = (const float*)d_in[0];   // [8192, 4096]
    const float* U    = (const float*)d_in[1];   // [4096, 256]
    const float* V    = (const float*)d_in[2];   // [256, 4096]
    const float* bias = (const float*)d_in[3];   // [4096]
    float* out = (float*)d_out;                  // [8192, 4096]

    float *vt, *ut, *T;
    cudaGetSymbolAddress((void**)&vt, g_vt);
    cudaGetSymbolAddress((void**)&ut, g_ut);
    cudaGetSymbolAddress((void**)&T,  g_t);

    cudaFuncSetAttribute(lr_gemm_s1, cudaFuncAttributeMaxDynamicSharedMemorySize, SMEM1_SZ);
    cudaFuncSetAttribute(lr_gemm_s2, cudaFuncAttributeMaxDynamicSharedMemorySize, SMEM2_SZ);

    // rna-round V and U (one tiny launch)
    const int n1 = 256 * 4096;
    cvt_vu<<<(2 * n1 / 4) / 256, 256>>>(V, vt, U, ut, n1);

    // Stage 1: T[8192,256] = x @ V^T (K=4096): 256 CTAs, occ 2, NST=4
    lr_gemm_s1<<<dim3(256 / 128, 8192 / 64), 256, SMEM1_SZ>>>(x, vt, 4096, 256, T);

    // Stage 2: out[8192,4096] = T @ U^T + bias (K=256): 2048 CTAs, occ 2
    lr_gemm_s2<<<dim3(4096 / 128, 8192 / 128), 256, SMEM2_SZ>>>(T, ut, 256, 4096, bias, out);
}